// round 3
// baseline (speedup 1.0000x reference)
#include <cuda_runtime.h>
#include <math.h>
#include <stdint.h>

// Problem dims
#define B_   64
#define T_   2048
#define IN_  512
#define H_   128
#define G3   384            // 3*H
#define EPS_ 1e-5f

// ---------------- device scratch ----------------
__device__ float g_xp[(size_t)2 * B_ * T_ * G3];      // [dir][B][T][3H]
__device__ float g_x1[(size_t)B_ * T_ * 2 * H_];      // [B][T][2H]
__device__ float g_hN[B_ * H_];

// ---------------- packed fp32x2 helpers ----------------
__device__ __forceinline__ unsigned long long ffma2(unsigned long long a,
                                                    unsigned long long b,
                                                    unsigned long long c) {
    unsigned long long d;
    asm("fma.rn.f32x2 %0, %1, %2, %3;" : "=l"(d) : "l"(a), "l"(b), "l"(c));
    return d;
}
__device__ __forceinline__ float2 u2f(unsigned long long u) {
    float2 f;
    asm("mov.b64 {%0, %1}, %2;" : "=f"(f.x), "=f"(f.y) : "l"(u));
    return f;
}
__device__ __forceinline__ unsigned long long dup2(float a) {
    unsigned long long d;
    asm("mov.b64 %0, {%1, %1};" : "=l"(d) : "f"(a));
    return d;
}
__device__ __forceinline__ float tanh_fast(float x) {
    float y;
    asm("tanh.approx.f32 %0, %1;" : "=f"(y) : "f"(x));
    return y;
}
__device__ __forceinline__ float sigmoid_fast(float x) {
    return fmaf(0.5f, tanh_fast(0.5f * x), 0.5f);
}

// =======================================================================
// Projection GEMM:  C[m][n] = sum_k A[m][k] * W[n][k] + bias[n]
// 128x128x16 tile, 256 threads, 8x8 micro-tile, FFMA2 inner loop.
// A stored PLAIN in smem (no duplication); (a,a) pairs built in regs.
// Double-buffered, one __syncthreads per k-tile. smem = 32 KB.
// =======================================================================
#define BM 128
#define BN 128
#define BK 16

__global__ __launch_bounds__(256, 2)
void proj_gemm(const float* __restrict__ A,          // null -> use g_x1
               int K,
               const float* __restrict__ W0, const float* __restrict__ bias0,
               const float* __restrict__ W1, const float* __restrict__ bias1)
{
    const float* Ap   = A ? A : g_x1;
    const float* W    = blockIdx.z ? W1 : W0;
    const float* bias = blockIdx.z ? bias1 : bias0;
    float* C = g_xp + (size_t)blockIdx.z * B_ * T_ * G3;

    __shared__ float As[2][BK][BM];   // 8 KB each
    __shared__ float Bs[2][BK][BN];   // 8 KB each

    const int tid = threadIdx.x;
    const int tx  = tid & 15;       // n-group
    const int ty  = tid >> 4;       // m-group
    const size_t rowA0 = (size_t)blockIdx.x * BM;
    const int    coln0 = blockIdx.y * BN;

    int lrow[2], lkq[2];
#pragma unroll
    for (int p = 0; p < 2; p++) {
        int f = p * 256 + tid;
        lrow[p] = f >> 2;
        lkq[p]  = (f & 3) * 4;
    }

    unsigned long long acc[8][4];
#pragma unroll
    for (int i = 0; i < 8; i++)
#pragma unroll
        for (int j = 0; j < 4; j++) acc[i][j] = 0ull;

    const int nkt = K / BK;

    float4 av[2], wv[2];
#pragma unroll
    for (int p = 0; p < 2; p++) {
        av[p] = *(const float4*)(Ap + (rowA0 + lrow[p]) * K + lkq[p]);
        wv[p] = *(const float4*)(W + (size_t)(coln0 + lrow[p]) * K + lkq[p]);
    }
#pragma unroll
    for (int p = 0; p < 2; p++) {
        int row = lrow[p], kq = lkq[p];
        As[0][kq + 0][row] = av[p].x;
        As[0][kq + 1][row] = av[p].y;
        As[0][kq + 2][row] = av[p].z;
        As[0][kq + 3][row] = av[p].w;
        Bs[0][kq + 0][row] = wv[p].x;
        Bs[0][kq + 1][row] = wv[p].y;
        Bs[0][kq + 2][row] = wv[p].z;
        Bs[0][kq + 3][row] = wv[p].w;
    }
    __syncthreads();

    for (int kt = 0; kt < nkt; kt++) {
        const int cur = kt & 1;
        const bool more = (kt + 1 < nkt);
        if (more) {
            const size_t ko = (size_t)(kt + 1) * BK;
#pragma unroll
            for (int p = 0; p < 2; p++) {
                av[p] = *(const float4*)(Ap + (rowA0 + lrow[p]) * K + ko + lkq[p]);
                wv[p] = *(const float4*)(W + (size_t)(coln0 + lrow[p]) * K + ko + lkq[p]);
            }
        }
#pragma unroll
        for (int kk = 0; kk < BK; kk++) {
            const float* as = &As[cur][kk][ty * 8];
            float4 af0 = *(const float4*)as;
            float4 af1 = *(const float4*)(as + 4);
            unsigned long long aq[8] = {
                dup2(af0.x), dup2(af0.y), dup2(af0.z), dup2(af0.w),
                dup2(af1.x), dup2(af1.y), dup2(af1.z), dup2(af1.w)
            };
            const ulonglong2* bpv = (const ulonglong2*)&Bs[cur][kk][tx * 8];
            ulonglong2 b0 = bpv[0], b1 = bpv[1];
            unsigned long long bq[4] = {b0.x, b0.y, b1.x, b1.y};
#pragma unroll
            for (int i = 0; i < 8; i++)
#pragma unroll
                for (int j = 0; j < 4; j++)
                    acc[i][j] = ffma2(aq[i], bq[j], acc[i][j]);
        }
        if (more) {
            const int nxt = cur ^ 1;
#pragma unroll
            for (int p = 0; p < 2; p++) {
                int row = lrow[p], kq = lkq[p];
                As[nxt][kq + 0][row] = av[p].x;
                As[nxt][kq + 1][row] = av[p].y;
                As[nxt][kq + 2][row] = av[p].z;
                As[nxt][kq + 3][row] = av[p].w;
                Bs[nxt][kq + 0][row] = wv[p].x;
                Bs[nxt][kq + 1][row] = wv[p].y;
                Bs[nxt][kq + 2][row] = wv[p].z;
                Bs[nxt][kq + 3][row] = wv[p].w;
            }
        }
        __syncthreads();
    }

    const int nb = coln0 + tx * 8;
    float bias8[8];
#pragma unroll
    for (int j = 0; j < 8; j++) bias8[j] = bias[nb + j];
#pragma unroll
    for (int i = 0; i < 8; i++) {
        size_t m = rowA0 + ty * 8 + i;
        float2 p0 = u2f(acc[i][0]), p1 = u2f(acc[i][1]);
        float2 p2 = u2f(acc[i][2]), p3 = u2f(acc[i][3]);
        float4 o0 = make_float4(p0.x + bias8[0], p0.y + bias8[1],
                                p1.x + bias8[2], p1.y + bias8[3]);
        float4 o1 = make_float4(p2.x + bias8[4], p2.y + bias8[5],
                                p3.x + bias8[6], p3.y + bias8[7]);
        *(float4*)(C + m * G3 + nb)     = o0;
        *(float4*)(C + m * G3 + nb + 4) = o1;
    }
}

// =======================================================================
// GRU sequential scan. One block per (direction, batch). 768 threads:
// TWO threads per gate output, each owning half the Whh row (64 floats
// = 64 regs), partner reduction via shfl_xor(1) (partners = adjacent
// lanes). Doubles warps/SMSP (latency hiding), halves per-thread LDS
// and FFMA2 chain depth vs the 384-thread version.
// =======================================================================
__global__ __launch_bounds__(768, 1)
void gru_scan(const float* __restrict__ WhhF, const float* __restrict__ bhhF,
              const float* __restrict__ WhhB, const float* __restrict__ bhhB,
              int write_x1, int write_hN, int ndir)
{
    int bid = blockIdx.x;
    int dir, b;
    if (ndir == 2) { dir = bid >> 6; b = bid & 63; }
    else           { dir = 1;        b = bid; }

    const float* Whh = dir ? WhhB : WhhF;
    const float* bhh = dir ? bhhB : bhhF;
    const float* xp = g_xp + ((size_t)((ndir == 2) ? dir : 0) * B_ + b) * (size_t)T_ * G3;

    const int tid  = threadIdx.x;
    const int out  = tid >> 1;      // 0..383
    const int half = tid & 1;       // which 64-wide half of the row

    __shared__ __align__(16) float sh_h[H_];
    __shared__ float sh_g[G3];
    __shared__ float sh_xn[H_];

    // half-row of Whh -> 32 packed pairs (64 regs)
    unsigned long long w[32];
    {
        const unsigned long long* wr =
            (const unsigned long long*)(Whh + (size_t)out * H_ + half * 64);
#pragma unroll
        for (int k = 0; k < 32; k++) w[k] = wr[k];
    }
    const float bj = bhh[out];
    if (tid < H_) sh_h[tid] = 0.f;
    __syncthreads();

    const int t0 = dir ? (T_ - 1) : 0;
    const int dt = dir ? -1 : 1;
    const ulonglong2* h4 = (const ulonglong2*)(sh_h + half * 64);

    float xv = xp[(size_t)t0 * G3 + out];

    for (int s = 0; s < T_; s++) {
        const int t = t0 + s * dt;
        float xv_next = 0.f;
        if (s + 1 < T_) xv_next = xp[(size_t)(t + dt) * G3 + out];

        unsigned long long acc0 = 0ull, acc1 = 0ull;
#pragma unroll
        for (int k = 0; k < 16; k++) {
            ulonglong2 hv = h4[k];                  // LDS.128
            acc0 = ffma2(hv.x, w[2 * k],     acc0);
            acc1 = ffma2(hv.y, w[2 * k + 1], acc1);
        }
        float2 a0 = u2f(acc0), a1 = u2f(acc1);
        float part = a0.x + a0.y + a1.x + a1.y;
        part += __shfl_xor_sync(0xffffffffu, part, 1);   // combine halves

        if (!half) {
            float g = part + bj;
            if (out < 2 * H_) { sh_g[out] = g + xv; }
            else              { sh_g[out] = g; sh_xn[out - 2 * H_] = xv; }
        }
        __syncthreads();

        if (tid < H_) {
            float r  = sigmoid_fast(sh_g[tid]);
            float z  = sigmoid_fast(sh_g[H_ + tid]);
            float n  = tanh_fast(sh_xn[tid] + r * sh_g[2 * H_ + tid]);
            float hn = (1.0f - z) * n + z * sh_h[tid];
            sh_h[tid] = hn;
            if (write_x1)
                g_x1[((size_t)b * T_ + t) * (2 * H_) + (size_t)dir * H_ + tid] = hn;
        }
        __syncthreads();
        xv = xv_next;
    }

    if (write_hN && tid < H_) g_hN[b * H_ + tid] = sh_h[tid];
}

// =======================================================================
// Decoder
// =======================================================================
__device__ __forceinline__ float mishf(float x) {
    float sp = (x > 20.f) ? x : log1pf(expf(x));
    return x * tanhf(sp);
}

__device__ __forceinline__ float blockReduceSum(float v) {
#pragma unroll
    for (int o = 16; o > 0; o >>= 1) v += __shfl_xor_sync(0xffffffffu, v, o);
    __shared__ float s[4];
    int w = threadIdx.x >> 5;
    if ((threadIdx.x & 31) == 0) s[w] = v;
    __syncthreads();
    v = s[0] + s[1] + s[2] + s[3];
    __syncthreads();
    return v;
}

__global__ __launch_bounds__(128, 1)
void decoder(const float* __restrict__ g1, const float* __restrict__ be1,
             const float* __restrict__ W1, const float* __restrict__ b1,
             const float* __restrict__ g2, const float* __restrict__ be2,
             const float* __restrict__ W2, const float* __restrict__ b2,
             float* __restrict__ out)
{
    const int b = blockIdx.x, j = threadIdx.x;
    __shared__ float sv[H_];

    float v = mishf(g_hN[b * H_ + j]);
    float m = blockReduceSum(v) * (1.0f / H_);
    float d = v - m;
    float var = blockReduceSum(d * d) * (1.0f / H_);
    float y = d * rsqrtf(var + EPS_) * g1[j] + be1[j];
    sv[j] = y;
    __syncthreads();

    float t = b1[j];
#pragma unroll 4
    for (int k = 0; k < H_; k++) t = fmaf(sv[k], W1[j * H_ + k], t);
    float u = mishf(t);
    __syncthreads();

    m = blockReduceSum(u) * (1.0f / H_);
    d = u - m;
    var = blockReduceSum(d * d) * (1.0f / H_);
    float zz = d * rsqrtf(var + EPS_) * g2[j] + be2[j];

    float p = blockReduceSum(zz * W2[j]);
    if (j == 0) out[b] = p + b2[0];
}

// =======================================================================
// Host launcher
// =======================================================================
extern "C" void kernel_launch(void* const* d_in, const int* in_sizes, int n_in,
                              void* d_out, int out_size)
{
    (void)in_sizes; (void)n_in; (void)out_size;
    const float* x     = (const float*)d_in[0];
    const float* Wih0f = (const float*)d_in[1];
    const float* Whh0f = (const float*)d_in[2];
    const float* bih0f = (const float*)d_in[3];
    const float* bhh0f = (const float*)d_in[4];
    const float* Wih0b = (const float*)d_in[5];
    const float* Whh0b = (const float*)d_in[6];
    const float* bih0b = (const float*)d_in[7];
    const float* bhh0b = (const float*)d_in[8];
    // d_in[9..12] = layer-1 forward params: unused by the reference output
    const float* Wih1b = (const float*)d_in[13];
    const float* Whh1b = (const float*)d_in[14];
    const float* bih1b = (const float*)d_in[15];
    const float* bhh1b = (const float*)d_in[16];
    const float* g1  = (const float*)d_in[17];
    const float* be1 = (const float*)d_in[18];
    const float* W1  = (const float*)d_in[19];
    const float* b1  = (const float*)d_in[20];
    const float* g2  = (const float*)d_in[21];
    const float* be2 = (const float*)d_in[22];
    const float* W2  = (const float*)d_in[23];
    const float* b2  = (const float*)d_in[24];

    {
        dim3 grid((B_ * T_) / BM, G3 / BN, 2);
        proj_gemm<<<grid, 256>>>(x, IN_, Wih0f, bih0f, Wih0b, bih0b);
    }
    gru_scan<<<128, 768>>>(Whh0f, bhh0f, Whh0b, bhh0b, 1, 0, 2);
    {
        dim3 grid((B_ * T_) / BM, G3 / BN, 1);
        proj_gemm<<<grid, 256>>>(nullptr, 2 * H_, Wih1b, bih1b, Wih1b, bih1b);
    }
    gru_scan<<<64, 768>>>(Whh1b, bhh1b, Whh1b, bhh1b, 0, 1, 1);
    decoder<<<64, 128>>>(g1, be1, W1, b1, g2, be2, W2, b2, (float*)d_out);
}

// round 4
// speedup vs baseline: 1.2870x; 1.2870x over previous
#include <cuda_runtime.h>
#include <math.h>
#include <stdint.h>

// Problem dims
#define B_   64
#define T_   2048
#define IN_  512
#define H_   128
#define G3   384            // 3*H
#define EPS_ 1e-5f

// ---------------- device scratch ----------------
__device__ float g_xp[(size_t)2 * B_ * T_ * G3];      // [dir][B][T][3H]
__device__ float g_x1[(size_t)B_ * T_ * 2 * H_];      // [B][T][2H]
__device__ float g_hN[B_ * H_];

// ---------------- packed fp32x2 helpers ----------------
__device__ __forceinline__ unsigned long long ffma2(unsigned long long a,
                                                    unsigned long long b,
                                                    unsigned long long c) {
    unsigned long long d;
    asm("fma.rn.f32x2 %0, %1, %2, %3;" : "=l"(d) : "l"(a), "l"(b), "l"(c));
    return d;
}
__device__ __forceinline__ float2 u2f(unsigned long long u) {
    float2 f;
    asm("mov.b64 {%0, %1}, %2;" : "=f"(f.x), "=f"(f.y) : "l"(u));
    return f;
}
__device__ __forceinline__ unsigned long long dup2(float a) {
    unsigned long long d;
    asm("mov.b64 %0, {%1, %1};" : "=l"(d) : "f"(a));
    return d;
}
__device__ __forceinline__ float tanh_fast(float x) {
    float y;
    asm("tanh.approx.f32 %0, %1;" : "=f"(y) : "f"(x));
    return y;
}
__device__ __forceinline__ float sigmoid_fast(float x) {
    return fmaf(0.5f, tanh_fast(0.5f * x), 0.5f);
}

// =======================================================================
// Projection GEMM:  C[m][n] = sum_k A[m][k] * W[n][k] + bias[n]
// 128x128x16 tile, 256 threads, 8x8 micro-tile, FFMA2 inner loop.
// A stored PLAIN in smem; (a,a) pairs built in regs (ALU pipe, hidden).
// Double-buffered, one __syncthreads per k-tile. smem = 32 KB.
// =======================================================================
#define BM 128
#define BN 128
#define BK 16

__global__ __launch_bounds__(256, 2)
void proj_gemm(const float* __restrict__ A,          // null -> use g_x1
               int K,
               const float* __restrict__ W0, const float* __restrict__ bias0,
               const float* __restrict__ W1, const float* __restrict__ bias1)
{
    const float* Ap   = A ? A : g_x1;
    const float* W    = blockIdx.z ? W1 : W0;
    const float* bias = blockIdx.z ? bias1 : bias0;
    float* C = g_xp + (size_t)blockIdx.z * B_ * T_ * G3;

    __shared__ float As[2][BK][BM];
    __shared__ float Bs[2][BK][BN];

    const int tid = threadIdx.x;
    const int tx  = tid & 15;
    const int ty  = tid >> 4;
    const size_t rowA0 = (size_t)blockIdx.x * BM;
    const int    coln0 = blockIdx.y * BN;

    int lrow[2], lkq[2];
#pragma unroll
    for (int p = 0; p < 2; p++) {
        int f = p * 256 + tid;
        lrow[p] = f >> 2;
        lkq[p]  = (f & 3) * 4;
    }

    unsigned long long acc[8][4];
#pragma unroll
    for (int i = 0; i < 8; i++)
#pragma unroll
        for (int j = 0; j < 4; j++) acc[i][j] = 0ull;

    const int nkt = K / BK;

    float4 av[2], wv[2];
#pragma unroll
    for (int p = 0; p < 2; p++) {
        av[p] = *(const float4*)(Ap + (rowA0 + lrow[p]) * K + lkq[p]);
        wv[p] = *(const float4*)(W + (size_t)(coln0 + lrow[p]) * K + lkq[p]);
    }
#pragma unroll
    for (int p = 0; p < 2; p++) {
        int row = lrow[p], kq = lkq[p];
        As[0][kq + 0][row] = av[p].x;
        As[0][kq + 1][row] = av[p].y;
        As[0][kq + 2][row] = av[p].z;
        As[0][kq + 3][row] = av[p].w;
        Bs[0][kq + 0][row] = wv[p].x;
        Bs[0][kq + 1][row] = wv[p].y;
        Bs[0][kq + 2][row] = wv[p].z;
        Bs[0][kq + 3][row] = wv[p].w;
    }
    __syncthreads();

    for (int kt = 0; kt < nkt; kt++) {
        const int cur = kt & 1;
        const bool more = (kt + 1 < nkt);
        if (more) {
            const size_t ko = (size_t)(kt + 1) * BK;
#pragma unroll
            for (int p = 0; p < 2; p++) {
                av[p] = *(const float4*)(Ap + (rowA0 + lrow[p]) * K + ko + lkq[p]);
                wv[p] = *(const float4*)(W + (size_t)(coln0 + lrow[p]) * K + ko + lkq[p]);
            }
        }
#pragma unroll
        for (int kk = 0; kk < BK; kk++) {
            const float* as = &As[cur][kk][ty * 8];
            float4 af0 = *(const float4*)as;
            float4 af1 = *(const float4*)(as + 4);
            unsigned long long aq[8] = {
                dup2(af0.x), dup2(af0.y), dup2(af0.z), dup2(af0.w),
                dup2(af1.x), dup2(af1.y), dup2(af1.z), dup2(af1.w)
            };
            const ulonglong2* bpv = (const ulonglong2*)&Bs[cur][kk][tx * 8];
            ulonglong2 b0 = bpv[0], b1 = bpv[1];
            unsigned long long bq[4] = {b0.x, b0.y, b1.x, b1.y};
#pragma unroll
            for (int i = 0; i < 8; i++)
#pragma unroll
                for (int j = 0; j < 4; j++)
                    acc[i][j] = ffma2(aq[i], bq[j], acc[i][j]);
        }
        if (more) {
            const int nxt = cur ^ 1;
#pragma unroll
            for (int p = 0; p < 2; p++) {
                int row = lrow[p], kq = lkq[p];
                As[nxt][kq + 0][row] = av[p].x;
                As[nxt][kq + 1][row] = av[p].y;
                As[nxt][kq + 2][row] = av[p].z;
                As[nxt][kq + 3][row] = av[p].w;
                Bs[nxt][kq + 0][row] = wv[p].x;
                Bs[nxt][kq + 1][row] = wv[p].y;
                Bs[nxt][kq + 2][row] = wv[p].z;
                Bs[nxt][kq + 3][row] = wv[p].w;
            }
        }
        __syncthreads();
    }

    const int nb = coln0 + tx * 8;
    float bias8[8];
#pragma unroll
    for (int j = 0; j < 8; j++) bias8[j] = bias[nb + j];
#pragma unroll
    for (int i = 0; i < 8; i++) {
        size_t m = rowA0 + ty * 8 + i;
        float2 p0 = u2f(acc[i][0]), p1 = u2f(acc[i][1]);
        float2 p2 = u2f(acc[i][2]), p3 = u2f(acc[i][3]);
        float4 o0 = make_float4(p0.x + bias8[0], p0.y + bias8[1],
                                p1.x + bias8[2], p1.y + bias8[3]);
        float4 o1 = make_float4(p2.x + bias8[4], p2.y + bias8[5],
                                p3.x + bias8[6], p3.y + bias8[7]);
        *(float4*)(C + m * G3 + nb)     = o0;
        *(float4*)(C + m * G3 + nb + 4) = o1;
    }
}

// =======================================================================
// GRU sequential scan. One block per (direction, batch). 384 threads,
// one per gate output (R2 shape: full Whh row in 128 regs, no spills).
// New vs R2: 2-deep xp prefetch (covers 577-cyc DRAM latency),
// split named barrier (producer warps arrive, gate warps sync),
// gate threads keep h_j in a register across steps.
// =======================================================================
__global__ __launch_bounds__(384, 1)
void gru_scan(const float* __restrict__ WhhF, const float* __restrict__ bhhF,
              const float* __restrict__ WhhB, const float* __restrict__ bhhB,
              int write_x1, int write_hN, int ndir)
{
    int bid = blockIdx.x;
    int dir, b;
    if (ndir == 2) { dir = bid >> 6; b = bid & 63; }
    else           { dir = 1;        b = bid; }

    const float* Whh = dir ? WhhB : WhhF;
    const float* bhh = dir ? bhhB : bhhF;
    const float* xp = g_xp + ((size_t)((ndir == 2) ? dir : 0) * B_ + b) * (size_t)T_ * G3;

    const int j = threadIdx.x;
    const bool is_gate = (j < H_);      // warps 0-3

    __shared__ __align__(16) float sh_h[H_];
    __shared__ float sh_g[G3];
    __shared__ float sh_xn[H_];

    // full Whh row -> 64 packed pairs (128 regs)
    unsigned long long w[H_ / 2];
    {
        const unsigned long long* wr =
            (const unsigned long long*)(Whh + (size_t)j * H_);
#pragma unroll
        for (int k = 0; k < H_ / 2; k++) w[k] = wr[k];
    }
    const float bj = bhh[j];
    if (is_gate) sh_h[j] = 0.f;
    float h_reg = 0.f;                  // gate threads' own h_j
    __syncthreads();

    const int t0 = dir ? (T_ - 1) : 0;
    const int dt = dir ? -1 : 1;
    const ulonglong2* h4 = (const ulonglong2*)sh_h;

    // 2-deep prefetch pipeline
    float xv0 = xp[(size_t)t0 * G3 + j];
    float xv1 = (T_ > 1) ? xp[(size_t)(t0 + dt) * G3 + j] : 0.f;

    for (int s = 0; s < T_; s++) {
        const int t = t0 + s * dt;
        float xv2 = 0.f;
        if (s + 2 < T_) xv2 = xp[(size_t)(t + 2 * dt) * G3 + j];

        unsigned long long acc0 = 0ull, acc1 = 0ull;
#pragma unroll
        for (int k = 0; k < H_ / 4; k++) {
            ulonglong2 hv = h4[k];                  // LDS.128 broadcast
            acc0 = ffma2(hv.x, w[2 * k],     acc0);
            acc1 = ffma2(hv.y, w[2 * k + 1], acc1);
        }
        float2 a0 = u2f(acc0), a1 = u2f(acc1);
        float g = a0.x + a0.y + a1.x + a1.y + bj;

        if (j < 2 * H_) { sh_g[j] = g + xv0; }
        else            { sh_g[j] = g; sh_xn[j - 2 * H_] = xv0; }

        if (is_gate) {
            asm volatile("bar.sync 1, 384;" ::: "memory");
            float r  = sigmoid_fast(sh_g[j]);
            float z  = sigmoid_fast(sh_g[H_ + j]);
            float n  = tanh_fast(sh_xn[j] + r * sh_g[2 * H_ + j]);
            float hn = (1.0f - z) * n + z * h_reg;
            h_reg = hn;
            sh_h[j] = hn;
            if (write_x1)
                g_x1[((size_t)b * T_ + t) * (2 * H_) + (size_t)dir * H_ + j] = hn;
        } else {
            asm volatile("bar.arrive 1, 384;" ::: "memory");
        }
        __syncthreads();                // h visible to all before next dot
        xv0 = xv1;
        xv1 = xv2;
    }

    if (write_hN && is_gate) g_hN[b * H_ + j] = h_reg;
}

// =======================================================================
// Decoder
// =======================================================================
__device__ __forceinline__ float mishf(float x) {
    float sp = (x > 20.f) ? x : log1pf(expf(x));
    return x * tanhf(sp);
}

__device__ __forceinline__ float blockReduceSum(float v) {
#pragma unroll
    for (int o = 16; o > 0; o >>= 1) v += __shfl_xor_sync(0xffffffffu, v, o);
    __shared__ float s[4];
    int w = threadIdx.x >> 5;
    if ((threadIdx.x & 31) == 0) s[w] = v;
    __syncthreads();
    v = s[0] + s[1] + s[2] + s[3];
    __syncthreads();
    return v;
}

__global__ __launch_bounds__(128, 1)
void decoder(const float* __restrict__ g1, const float* __restrict__ be1,
             const float* __restrict__ W1, const float* __restrict__ b1,
             const float* __restrict__ g2, const float* __restrict__ be2,
             const float* __restrict__ W2, const float* __restrict__ b2,
             float* __restrict__ out)
{
    const int b = blockIdx.x, j = threadIdx.x;
    __shared__ float sv[H_];

    float v = mishf(g_hN[b * H_ + j]);
    float m = blockReduceSum(v) * (1.0f / H_);
    float d = v - m;
    float var = blockReduceSum(d * d) * (1.0f / H_);
    float y = d * rsqrtf(var + EPS_) * g1[j] + be1[j];
    sv[j] = y;
    __syncthreads();

    float t = b1[j];
#pragma unroll 4
    for (int k = 0; k < H_; k++) t = fmaf(sv[k], W1[j * H_ + k], t);
    float u = mishf(t);
    __syncthreads();

    m = blockReduceSum(u) * (1.0f / H_);
    d = u - m;
    var = blockReduceSum(d * d) * (1.0f / H_);
    float zz = d * rsqrtf(var + EPS_) * g2[j] + be2[j];

    float p = blockReduceSum(zz * W2[j]);
    if (j == 0) out[b] = p + b2[0];
}

// =======================================================================
// Host launcher
// =======================================================================
extern "C" void kernel_launch(void* const* d_in, const int* in_sizes, int n_in,
                              void* d_out, int out_size)
{
    (void)in_sizes; (void)n_in; (void)out_size;
    const float* x     = (const float*)d_in[0];
    const float* Wih0f = (const float*)d_in[1];
    const float* Whh0f = (const float*)d_in[2];
    const float* bih0f = (const float*)d_in[3];
    const float* bhh0f = (const float*)d_in[4];
    const float* Wih0b = (const float*)d_in[5];
    const float* Whh0b = (const float*)d_in[6];
    const float* bih0b = (const float*)d_in[7];
    const float* bhh0b = (const float*)d_in[8];
    // d_in[9..12] = layer-1 forward params: unused by the reference output
    const float* Wih1b = (const float*)d_in[13];
    const float* Whh1b = (const float*)d_in[14];
    const float* bih1b = (const float*)d_in[15];
    const float* bhh1b = (const float*)d_in[16];
    const float* g1  = (const float*)d_in[17];
    const float* be1 = (const float*)d_in[18];
    const float* W1  = (const float*)d_in[19];
    const float* b1  = (const float*)d_in[20];
    const float* g2  = (const float*)d_in[21];
    const float* be2 = (const float*)d_in[22];
    const float* W2  = (const float*)d_in[23];
    const float* b2  = (const float*)d_in[24];

    {
        dim3 grid((B_ * T_) / BM, G3 / BN, 2);
        proj_gemm<<<grid, 256>>>(x, IN_, Wih0f, bih0f, Wih0b, bih0b);
    }
    gru_scan<<<128, 384>>>(Whh0f, bhh0f, Whh0b, bhh0b, 1, 0, 2);
    {
        dim3 grid((B_ * T_) / BM, G3 / BN, 1);
        proj_gemm<<<grid, 256>>>(nullptr, 2 * H_, Wih1b, bih1b, Wih1b, bih1b);
    }
    gru_scan<<<64, 384>>>(Whh1b, bhh1b, Whh1b, bhh1b, 0, 1, 1);
    decoder<<<64, 128>>>(g1, be1, W1, b1, g2, be2, W2, b2, (float*)d_out);
}

// round 7
// speedup vs baseline: 1.8388x; 1.4287x over previous
#include <cuda_runtime.h>
#include <cuda_bf16.h>
#include <math.h>
#include <stdint.h>

// Problem dims
#define B_   64
#define T_   2048
#define IN_  512
#define H_   128
#define G3   384            // 3*H
#define EPS_ 1e-5f
#define MTOT (B_ * T_)      // 131072

// ---------------- device scratch ----------------
__device__ float g_xp[(size_t)2 * B_ * T_ * G3];              // [dir][B][T][3H] fp32
__device__ __nv_bfloat16 g_xh[(size_t)MTOT * IN_];
__device__ __nv_bfloat16 g_xl[(size_t)MTOT * IN_];
__device__ __nv_bfloat16 g_x1h[(size_t)MTOT * 2 * H_];
__device__ __nv_bfloat16 g_x1l[(size_t)MTOT * 2 * H_];
__device__ __nv_bfloat16 g_w0fh[G3 * IN_], g_w0fl[G3 * IN_];
__device__ __nv_bfloat16 g_w0bh[G3 * IN_], g_w0bl[G3 * IN_];
__device__ __nv_bfloat16 g_w1bh[G3 * 2 * H_], g_w1bl[G3 * 2 * H_];
__device__ float g_hN[B_ * H_];

// ---------------- helpers ----------------
__device__ __forceinline__ unsigned long long ffma2(unsigned long long a,
                                                    unsigned long long b,
                                                    unsigned long long c) {
    unsigned long long d;
    asm("fma.rn.f32x2 %0, %1, %2, %3;" : "=l"(d) : "l"(a), "l"(b), "l"(c));
    return d;
}
__device__ __forceinline__ float2 u2f(unsigned long long u) {
    float2 f;
    asm("mov.b64 {%0, %1}, %2;" : "=f"(f.x), "=f"(f.y) : "l"(u));
    return f;
}
__device__ __forceinline__ float tanh_fast(float x) {
    float y;
    asm("tanh.approx.f32 %0, %1;" : "=f"(y) : "f"(x));
    return y;
}
__device__ __forceinline__ float sigmoid_fast(float x) {
    return fmaf(0.5f, tanh_fast(0.5f * x), 0.5f);
}
__device__ __forceinline__ void cp16(uint32_t dst, const void* src) {
    asm volatile("cp.async.cg.shared.global [%0], [%1], 16;" :: "r"(dst), "l"(src));
}
__device__ __forceinline__ uint32_t s2u(const void* p) {
    uint32_t a;
    asm("{ .reg .u64 t; cvta.to.shared.u64 t, %1; cvt.u32.u64 %0, t; }"
        : "=r"(a) : "l"(p));
    return a;
}
__device__ __forceinline__ uint32_t lds32(uint32_t a) {
    uint32_t v;
    asm volatile("ld.shared.b32 %0, [%1];" : "=r"(v) : "r"(a));
    return v;
}
__device__ __forceinline__ void mma16816(float* c, uint32_t a0, uint32_t a1,
                                         uint32_t a2, uint32_t a3,
                                         uint32_t b0, uint32_t b1) {
    asm volatile(
        "mma.sync.aligned.m16n8k16.row.col.f32.bf16.bf16.f32 "
        "{%0,%1,%2,%3}, {%4,%5,%6,%7}, {%8,%9}, {%0,%1,%2,%3};"
        : "+f"(c[0]), "+f"(c[1]), "+f"(c[2]), "+f"(c[3])
        : "r"(a0), "r"(a1), "r"(a2), "r"(a3), "r"(b0), "r"(b1));
}

// =======================================================================
// Split fp32 -> bf16 (hi, lo)
// =======================================================================
__global__ void split_bf16(const float* __restrict__ src,
                           __nv_bfloat16* __restrict__ dh,
                           __nv_bfloat16* __restrict__ dl, size_t n)
{
    size_t i = ((size_t)blockIdx.x * blockDim.x + threadIdx.x) * 4;
    size_t stride = (size_t)gridDim.x * blockDim.x * 4;
    for (; i < n; i += stride) {
        float4 v = *(const float4*)(src + i);
        __nv_bfloat16 h0 = __float2bfloat16(v.x);
        __nv_bfloat16 h1 = __float2bfloat16(v.y);
        __nv_bfloat16 h2 = __float2bfloat16(v.z);
        __nv_bfloat16 h3 = __float2bfloat16(v.w);
        __nv_bfloat16 l0 = __float2bfloat16(v.x - __bfloat162float(h0));
        __nv_bfloat16 l1 = __float2bfloat16(v.y - __bfloat162float(h1));
        __nv_bfloat16 l2 = __float2bfloat16(v.z - __bfloat162float(h2));
        __nv_bfloat16 l3 = __float2bfloat16(v.w - __bfloat162float(h3));
        *(__nv_bfloat162*)(dh + i)     = __nv_bfloat162(h0, h1);
        *(__nv_bfloat162*)(dh + i + 2) = __nv_bfloat162(h2, h3);
        *(__nv_bfloat162*)(dl + i)     = __nv_bfloat162(l0, l1);
        *(__nv_bfloat162*)(dl + i + 2) = __nv_bfloat162(l2, l3);
    }
}

// =======================================================================
// HMMA split-bf16 GEMM: C[m][n] = sum_k A[m][k]*W[n][k] + bias[n]
// D += Ah*Wh + Ah*Wl + Al*Wh  (fp32 register accumulators).
// CTA: 128(M) x 128(N), 8 warps (2m x 4n), warp tile m64n32.
// k-chunk 32, cp.async double buffered. Smem rows padded to 40 bf16
// (conflict-free for the m16n8k16 fragment pattern).
// =======================================================================
#define SA 40                 // padded row stride in bf16
#define TILEB (128 * SA)      // one array, bf16 units (5120)
#define BUFB  (4 * TILEB)     // Ah,Al,Wh,Wl (20480 bf16)
#define HG_SMEM (2 * BUFB * 2 + 512)   // 81920 + 512 bias bytes

__global__ __launch_bounds__(256, 2)
void hmma_gemm(const __nv_bfloat16* __restrict__ Ah,
               const __nv_bfloat16* __restrict__ Al, int K,
               const __nv_bfloat16* __restrict__ Wh0,
               const __nv_bfloat16* __restrict__ Wl0, const float* __restrict__ b0,
               const __nv_bfloat16* __restrict__ Wh1,
               const __nv_bfloat16* __restrict__ Wl1, const float* __restrict__ b1)
{
    extern __shared__ __nv_bfloat16 sm[];
    const __nv_bfloat16* Wh = blockIdx.z ? Wh1 : Wh0;
    const __nv_bfloat16* Wl = blockIdx.z ? Wl1 : Wl0;
    const float* bias = blockIdx.z ? b1 : b0;
    float* C = g_xp + (size_t)blockIdx.z * MTOT * G3;

    float* sbias = (float*)(sm + 2 * BUFB);
    const uint32_t smu = s2u(sm);

    const int tid  = threadIdx.x;
    const int wid  = tid >> 5;
    const int lane = tid & 31;
    const int wm   = wid >> 2;          // 0..1
    const int wn   = wid & 3;           // 0..3
    const int g    = lane >> 2;         // 0..7
    const int t    = lane & 3;          // 0..3

    const size_t rowA0 = (size_t)blockIdx.x * 128;
    const int    ncol0 = blockIdx.y * 128;

    if (tid < 128) sbias[tid] = bias[ncol0 + tid];

    // per-thread cp.async coordinates: u in 0..511 (2 per array)
    int lrow[2], lq[2];
#pragma unroll
    for (int p = 0; p < 2; p++) {
        int u = p * 256 + tid;
        lrow[p] = u >> 2;
        lq[p]   = u & 3;
    }

    float c[4][4][4];
#pragma unroll
    for (int i = 0; i < 4; i++)
#pragma unroll
        for (int j = 0; j < 4; j++)
#pragma unroll
            for (int q = 0; q < 4; q++) c[i][j][q] = 0.f;

    const int nkt = K / 32;

    // tile loader: buffer b, k-tile kt
    auto load_tile = [&](int kt, int b) {
        uint32_t base = smu + (uint32_t)b * BUFB * 2;
#pragma unroll
        for (int p = 0; p < 2; p++) {
            int row = lrow[p], q = lq[p];
            uint32_t doff = (uint32_t)(row * SA + q * 8) * 2;
            size_t ga = (rowA0 + row) * (size_t)K + (size_t)kt * 32 + q * 8;
            size_t gw = ((size_t)ncol0 + row) * (size_t)K + (size_t)kt * 32 + q * 8;
            cp16(base + 0 * TILEB * 2 + doff, Ah + ga);
            cp16(base + 1 * TILEB * 2 + doff, Al + ga);
            cp16(base + 2 * TILEB * 2 + doff, Wh + gw);
            cp16(base + 3 * TILEB * 2 + doff, Wl + gw);
        }
    };

    load_tile(0, 0);
    asm volatile("cp.async.commit_group;");

    for (int kt = 0; kt < nkt; kt++) {
        if (kt + 1 < nkt) {
            load_tile(kt + 1, (kt + 1) & 1);
            asm volatile("cp.async.commit_group;");
            asm volatile("cp.async.wait_group 1;");
        } else {
            asm volatile("cp.async.wait_group 0;");
        }
        __syncthreads();

        const uint32_t buf = smu + (uint32_t)(kt & 1) * BUFB * 2;
        // combo: 0 = Ah*Wh, 1 = Ah*Wl, 2 = Al*Wh
#pragma unroll
        for (int combo = 0; combo < 3; combo++) {
            const uint32_t Ab = buf + (combo == 2 ? 1 : 0) * TILEB * 2;
            const uint32_t Wb = buf + (combo == 1 ? 3 : 2) * TILEB * 2;
#pragma unroll
            for (int ks = 0; ks < 2; ks++) {
                const int kof = ks * 16 + 2 * t;        // bf16 units
                // B fragments for 4 n-subtiles
                uint32_t bf[4][2];
#pragma unroll
                for (int j = 0; j < 4; j++) {
                    uint32_t nrow = (uint32_t)(wn * 32 + j * 8 + g);
                    uint32_t ad = Wb + (nrow * SA + kof) * 2;
                    bf[j][0] = lds32(ad);
                    bf[j][1] = lds32(ad + 16);          // k +8 -> +16B
                }
#pragma unroll
                for (int i = 0; i < 4; i++) {
                    uint32_t mrow = (uint32_t)(wm * 64 + i * 16 + g);
                    uint32_t ad = Ab + (mrow * SA + kof) * 2;
                    uint32_t a0 = lds32(ad);
                    uint32_t a1 = lds32(ad + SA * 8 * 2);       // row +8
                    uint32_t a2 = lds32(ad + 16);               // k +8
                    uint32_t a3 = lds32(ad + SA * 8 * 2 + 16);
#pragma unroll
                    for (int j = 0; j < 4; j++)
                        mma16816(c[i][j], a0, a1, a2, a3, bf[j][0], bf[j][1]);
                }
            }
        }
        __syncthreads();
    }

    // epilogue: c0,c1 -> (row g, col 2t..2t+1); c2,c3 -> (row g+8)
#pragma unroll
    for (int i = 0; i < 4; i++) {
        size_t r0 = rowA0 + wm * 64 + i * 16 + g;
        size_t r1 = r0 + 8;
#pragma unroll
        for (int j = 0; j < 4; j++) {
            int cl = wn * 32 + j * 8 + 2 * t;           // 0..127 within tile
            float b0v = sbias[cl], b1v = sbias[cl + 1];
            *(float2*)(C + r0 * G3 + ncol0 + cl) =
                make_float2(c[i][j][0] + b0v, c[i][j][1] + b1v);
            *(float2*)(C + r1 * G3 + ncol0 + cl) =
                make_float2(c[i][j][2] + b0v, c[i][j][3] + b1v);
        }
    }
}

// =======================================================================
// GRU sequential scan (R4 winning shape). Layer-0 writes x1 as bf16 hi/lo.
// =======================================================================
__global__ __launch_bounds__(384, 1)
void gru_scan(const float* __restrict__ WhhF, const float* __restrict__ bhhF,
              const float* __restrict__ WhhB, const float* __restrict__ bhhB,
              int write_x1, int write_hN, int ndir)
{
    int bid = blockIdx.x;
    int dir, b;
    if (ndir == 2) { dir = bid >> 6; b = bid & 63; }
    else           { dir = 1;        b = bid; }

    const float* Whh = dir ? WhhB : WhhF;
    const float* bhh = dir ? bhhB : bhhF;
    const float* xp = g_xp + ((size_t)((ndir == 2) ? dir : 0) * B_ + b) * (size_t)T_ * G3;

    const int j = threadIdx.x;
    const bool is_gate = (j < H_);

    __shared__ __align__(16) float sh_h[H_];
    __shared__ float sh_g[G3];
    __shared__ float sh_xn[H_];

    unsigned long long w[H_ / 2];
    {
        const unsigned long long* wr =
            (const unsigned long long*)(Whh + (size_t)j * H_);
#pragma unroll
        for (int k = 0; k < H_ / 2; k++) w[k] = wr[k];
    }
    const float bj = bhh[j];
    if (is_gate) sh_h[j] = 0.f;
    float h_reg = 0.f;
    __syncthreads();

    const int t0 = dir ? (T_ - 1) : 0;
    const int dt = dir ? -1 : 1;
    const ulonglong2* h4 = (const ulonglong2*)sh_h;

    float xv0 = xp[(size_t)t0 * G3 + j];
    float xv1 = (T_ > 1) ? xp[(size_t)(t0 + dt) * G3 + j] : 0.f;

    for (int s = 0; s < T_; s++) {
        const int t = t0 + s * dt;
        float xv2 = 0.f;
        if (s + 2 < T_) xv2 = xp[(size_t)(t + 2 * dt) * G3 + j];

        unsigned long long acc0 = 0ull, acc1 = 0ull;
#pragma unroll
        for (int k = 0; k < H_ / 4; k++) {
            ulonglong2 hv = h4[k];
            acc0 = ffma2(hv.x, w[2 * k],     acc0);
            acc1 = ffma2(hv.y, w[2 * k + 1], acc1);
        }
        float2 a0 = u2f(acc0), a1 = u2f(acc1);
        float g = a0.x + a0.y + a1.x + a1.y + bj;

        if (j < 2 * H_) { sh_g[j] = g + xv0; }
        else            { sh_g[j] = g; sh_xn[j - 2 * H_] = xv0; }

        if (is_gate) {
            asm volatile("bar.sync 1, 384;" ::: "memory");
            float r  = sigmoid_fast(sh_g[j]);
            float z  = sigmoid_fast(sh_g[H_ + j]);
            float n  = tanh_fast(sh_xn[j] + r * sh_g[2 * H_ + j]);
            float hn = (1.0f - z) * n + z * h_reg;
            h_reg = hn;
            sh_h[j] = hn;
            if (write_x1) {
                size_t idx = ((size_t)b * T_ + t) * (2 * H_) + (size_t)dir * H_ + j;
                __nv_bfloat16 hi = __float2bfloat16(hn);
                g_x1h[idx] = hi;
                g_x1l[idx] = __float2bfloat16(hn - __bfloat162float(hi));
            }
        } else {
            asm volatile("bar.arrive 1, 384;" ::: "memory");
        }
        __syncthreads();
        xv0 = xv1;
        xv1 = xv2;
    }

    if (write_hN && is_gate) g_hN[b * H_ + j] = h_reg;
}

// =======================================================================
// Decoder
// =======================================================================
__device__ __forceinline__ float mishf(float x) {
    float sp = (x > 20.f) ? x : log1pf(expf(x));
    return x * tanhf(sp);
}
__device__ __forceinline__ float blockReduceSum(float v) {
#pragma unroll
    for (int o = 16; o > 0; o >>= 1) v += __shfl_xor_sync(0xffffffffu, v, o);
    __shared__ float s[4];
    int w = threadIdx.x >> 5;
    if ((threadIdx.x & 31) == 0) s[w] = v;
    __syncthreads();
    v = s[0] + s[1] + s[2] + s[3];
    __syncthreads();
    return v;
}

__global__ __launch_bounds__(128, 1)
void decoder(const float* __restrict__ g1, const float* __restrict__ be1,
             const float* __restrict__ W1, const float* __restrict__ b1,
             const float* __restrict__ g2, const float* __restrict__ be2,
             const float* __restrict__ W2, const float* __restrict__ b2,
             float* __restrict__ out)
{
    const int b = blockIdx.x, j = threadIdx.x;
    __shared__ float sv[H_];

    float v = mishf(g_hN[b * H_ + j]);
    float m = blockReduceSum(v) * (1.0f / H_);
    float d = v - m;
    float var = blockReduceSum(d * d) * (1.0f / H_);
    float y = d * rsqrtf(var + EPS_) * g1[j] + be1[j];
    sv[j] = y;
    __syncthreads();

    float t = b1[j];
#pragma unroll 4
    for (int k = 0; k < H_; k++) t = fmaf(sv[k], W1[j * H_ + k], t);
    float u = mishf(t);
    __syncthreads();

    m = blockReduceSum(u) * (1.0f / H_);
    d = u - m;
    var = blockReduceSum(d * d) * (1.0f / H_);
    float zz = d * rsqrtf(var + EPS_) * g2[j] + be2[j];

    float p = blockReduceSum(zz * W2[j]);
    if (j == 0) out[b] = p + b2[0];
}

// =======================================================================
// Host launcher
// =======================================================================
extern "C" void kernel_launch(void* const* d_in, const int* in_sizes, int n_in,
                              void* d_out, int out_size)
{
    (void)in_sizes; (void)n_in; (void)out_size;
    const float* x     = (const float*)d_in[0];
    const float* Wih0f = (const float*)d_in[1];
    const float* Whh0f = (const float*)d_in[2];
    const float* bih0f = (const float*)d_in[3];
    const float* bhh0f = (const float*)d_in[4];
    const float* Wih0b = (const float*)d_in[5];
    const float* Whh0b = (const float*)d_in[6];
    const float* bih0b = (const float*)d_in[7];
    const float* bhh0b = (const float*)d_in[8];
    // d_in[9..12] = layer-1 forward params: unused by the reference output
    const float* Wih1b = (const float*)d_in[13];
    const float* Whh1b = (const float*)d_in[14];
    const float* bih1b = (const float*)d_in[15];
    const float* bhh1b = (const float*)d_in[16];
    const float* g1  = (const float*)d_in[17];
    const float* be1 = (const float*)d_in[18];
    const float* W1  = (const float*)d_in[19];
    const float* b1  = (const float*)d_in[20];
    const float* g2  = (const float*)d_in[21];
    const float* be2 = (const float*)d_in[22];
    const float* W2  = (const float*)d_in[23];
    const float* b2  = (const float*)d_in[24];

    __nv_bfloat16 *xh, *xl, *w0fh, *w0fl, *w0bh, *w0bl, *w1bh, *w1bl, *x1h, *x1l;
    cudaGetSymbolAddress((void**)&xh,   g_xh);
    cudaGetSymbolAddress((void**)&xl,   g_xl);
    cudaGetSymbolAddress((void**)&w0fh, g_w0fh);
    cudaGetSymbolAddress((void**)&w0fl, g_w0fl);
    cudaGetSymbolAddress((void**)&w0bh, g_w0bh);
    cudaGetSymbolAddress((void**)&w0bl, g_w0bl);
    cudaGetSymbolAddress((void**)&w1bh, g_w1bh);
    cudaGetSymbolAddress((void**)&w1bl, g_w1bl);
    cudaGetSymbolAddress((void**)&x1h,  g_x1h);
    cudaGetSymbolAddress((void**)&x1l,  g_x1l);

    static int smem_set = 0;
    if (!smem_set) {
        cudaFuncSetAttribute(hmma_gemm,
                             cudaFuncAttributeMaxDynamicSharedMemorySize, HG_SMEM);
        smem_set = 1;
    }

    // split inputs into bf16 hi/lo
    split_bf16<<<4096, 256>>>(x, xh, xl, (size_t)MTOT * IN_);
    split_bf16<<<64, 256>>>(Wih0f, w0fh, w0fl, (size_t)G3 * IN_);
    split_bf16<<<64, 256>>>(Wih0b, w0bh, w0bl, (size_t)G3 * IN_);
    split_bf16<<<32, 256>>>(Wih1b, w1bh, w1bl, (size_t)G3 * 2 * H_);

    // layer-0 projections: grid z = dir, y = n-tile (3 of 128)
    {
        dim3 grid(MTOT / 128, 3, 2);
        hmma_gemm<<<grid, 256, HG_SMEM>>>(xh, xl, IN_,
                                          w0fh, w0fl, bih0f,
                                          w0bh, w0bl, bih0b);
    }
    gru_scan<<<128, 384>>>(Whh0f, bhh0f, Whh0b, bhh0b, 1, 0, 2);
    // layer-1 backward projection
    {
        dim3 grid(MTOT / 128, 3, 1);
        hmma_gemm<<<grid, 256, HG_SMEM>>>(x1h, x1l, 2 * H_,
                                          w1bh, w1bl, bih1b,
                                          w1bh, w1bl, bih1b);
    }
    gru_scan<<<64, 384>>>(Whh1b, bhh1b, Whh1b, bhh1b, 0, 1, 1);
    decoder<<<64, 128>>>(g1, be1, W1, b1, g2, be2, W2, b2, (float*)d_out);
}

// round 8
// speedup vs baseline: 1.9594x; 1.0656x over previous
#include <cuda_runtime.h>
#include <cuda_bf16.h>
#include <math.h>
#include <stdint.h>

// Problem dims
#define B_   64
#define T_   2048
#define IN_  512
#define H_   128
#define G3   384            // 3*H
#define EPS_ 1e-5f
#define MTOT (B_ * T_)      // 131072

// ---------------- device scratch ----------------
__device__ float g_xp[(size_t)2 * B_ * T_ * G3];              // [dir][B][T][3H] fp32
__device__ __nv_bfloat16 g_xh[(size_t)MTOT * IN_];
__device__ __nv_bfloat16 g_xl[(size_t)MTOT * IN_];
__device__ __nv_bfloat16 g_x1h[(size_t)MTOT * 2 * H_];
__device__ __nv_bfloat16 g_x1l[(size_t)MTOT * 2 * H_];
__device__ __nv_bfloat16 g_w0fh[G3 * IN_], g_w0fl[G3 * IN_];
__device__ __nv_bfloat16 g_w0bh[G3 * IN_], g_w0bl[G3 * IN_];
__device__ __nv_bfloat16 g_w1bh[G3 * 2 * H_], g_w1bl[G3 * 2 * H_];
__device__ float g_hN[B_ * H_];

// ---------------- helpers ----------------
__device__ __forceinline__ unsigned long long ffma2(unsigned long long a,
                                                    unsigned long long b,
                                                    unsigned long long c) {
    unsigned long long d;
    asm("fma.rn.f32x2 %0, %1, %2, %3;" : "=l"(d) : "l"(a), "l"(b), "l"(c));
    return d;
}
__device__ __forceinline__ float2 u2f(unsigned long long u) {
    float2 f;
    asm("mov.b64 {%0, %1}, %2;" : "=f"(f.x), "=f"(f.y) : "l"(u));
    return f;
}
__device__ __forceinline__ float tanh_fast(float x) {
    float y;
    asm("tanh.approx.f32 %0, %1;" : "=f"(y) : "f"(x));
    return y;
}
__device__ __forceinline__ float sigmoid_fast(float x) {
    return fmaf(0.5f, tanh_fast(0.5f * x), 0.5f);
}
__device__ __forceinline__ void cp16(uint32_t dst, const void* src) {
    asm volatile("cp.async.cg.shared.global [%0], [%1], 16;" :: "r"(dst), "l"(src));
}
__device__ __forceinline__ uint32_t s2u(const void* p) {
    uint32_t a;
    asm("{ .reg .u64 t; cvta.to.shared.u64 t, %1; cvt.u32.u64 %0, t; }"
        : "=r"(a) : "l"(p));
    return a;
}
__device__ __forceinline__ uint32_t lds32(uint32_t a) {
    uint32_t v;
    asm volatile("ld.shared.b32 %0, [%1];" : "=r"(v) : "r"(a));
    return v;
}
__device__ __forceinline__ void mma16816(float* c, uint32_t a0, uint32_t a1,
                                         uint32_t a2, uint32_t a3,
                                         uint32_t b0, uint32_t b1) {
    asm volatile(
        "mma.sync.aligned.m16n8k16.row.col.f32.bf16.bf16.f32 "
        "{%0,%1,%2,%3}, {%4,%5,%6,%7}, {%8,%9}, {%0,%1,%2,%3};"
        : "+f"(c[0]), "+f"(c[1]), "+f"(c[2]), "+f"(c[3])
        : "r"(a0), "r"(a1), "r"(a2), "r"(a3), "r"(b0), "r"(b1));
}

// =======================================================================
// Split fp32 -> bf16 (hi, lo)
// =======================================================================
__global__ void split_bf16(const float* __restrict__ src,
                           __nv_bfloat16* __restrict__ dh,
                           __nv_bfloat16* __restrict__ dl, size_t n)
{
    size_t i = ((size_t)blockIdx.x * blockDim.x + threadIdx.x) * 4;
    size_t stride = (size_t)gridDim.x * blockDim.x * 4;
    for (; i < n; i += stride) {
        float4 v = *(const float4*)(src + i);
        __nv_bfloat16 h0 = __float2bfloat16(v.x);
        __nv_bfloat16 h1 = __float2bfloat16(v.y);
        __nv_bfloat16 h2 = __float2bfloat16(v.z);
        __nv_bfloat16 h3 = __float2bfloat16(v.w);
        __nv_bfloat16 l0 = __float2bfloat16(v.x - __bfloat162float(h0));
        __nv_bfloat16 l1 = __float2bfloat16(v.y - __bfloat162float(h1));
        __nv_bfloat16 l2 = __float2bfloat16(v.z - __bfloat162float(h2));
        __nv_bfloat16 l3 = __float2bfloat16(v.w - __bfloat162float(h3));
        *(__nv_bfloat162*)(dh + i)     = __nv_bfloat162(h0, h1);
        *(__nv_bfloat162*)(dh + i + 2) = __nv_bfloat162(h2, h3);
        *(__nv_bfloat162*)(dl + i)     = __nv_bfloat162(l0, l1);
        *(__nv_bfloat162*)(dl + i + 2) = __nv_bfloat162(l2, l3);
    }
}

// =======================================================================
// HMMA split-bf16 GEMM with software-pipelined fragment stages.
// CTA: 128(M) x 128(N), 8 warps (2m x 4n), warp tile m64n32.
// grid: (n-tile=3 fastest, m-tile, dir) -> A tile L2 reuse across n-tiles.
// =======================================================================
#define SA 40                 // padded row stride in bf16
#define TILEB (128 * SA)      // 5120 bf16 per array
#define BUFB  (4 * TILEB)     // Ah,Al,Wh,Wl
#define HG_SMEM (2 * BUFB * 2 + 512)

__global__ __launch_bounds__(256, 2)
void hmma_gemm(const __nv_bfloat16* __restrict__ Ah,
               const __nv_bfloat16* __restrict__ Al, int K,
               const __nv_bfloat16* __restrict__ Wh0,
               const __nv_bfloat16* __restrict__ Wl0, const float* __restrict__ b0,
               const __nv_bfloat16* __restrict__ Wh1,
               const __nv_bfloat16* __restrict__ Wl1, const float* __restrict__ b1)
{
    extern __shared__ __nv_bfloat16 sm[];
    const __nv_bfloat16* Wh = blockIdx.z ? Wh1 : Wh0;
    const __nv_bfloat16* Wl = blockIdx.z ? Wl1 : Wl0;
    const float* bias = blockIdx.z ? b1 : b0;
    float* C = g_xp + (size_t)blockIdx.z * MTOT * G3;

    float* sbias = (float*)(sm + 2 * BUFB);
    const uint32_t smu = s2u(sm);

    const int tid  = threadIdx.x;
    const int wid  = tid >> 5;
    const int lane = tid & 31;
    const int wm   = wid >> 2;
    const int wn   = wid & 3;
    const int g    = lane >> 3;         // unused placeholder (kept minimal)
    const int gg   = lane >> 2;         // 0..7
    const int t    = lane & 3;          // 0..3
    (void)g;

    const size_t rowA0 = (size_t)blockIdx.y * 128;   // m-tile
    const int    ncol0 = blockIdx.x * 128;           // n-tile (fastest)

    if (tid < 128) sbias[tid] = bias[ncol0 + tid];

    int lrow[2], lq[2];
#pragma unroll
    for (int p = 0; p < 2; p++) {
        int u = p * 256 + tid;
        lrow[p] = u >> 2;
        lq[p]   = u & 3;
    }

    float c[4][4][4];
#pragma unroll
    for (int i = 0; i < 4; i++)
#pragma unroll
        for (int j = 0; j < 4; j++)
#pragma unroll
            for (int q = 0; q < 4; q++) c[i][j][q] = 0.f;

    const int nkt = K / 32;

    auto load_tile = [&](int kt, int b) {
        uint32_t base = smu + (uint32_t)b * BUFB * 2;
#pragma unroll
        for (int p = 0; p < 2; p++) {
            int row = lrow[p], q = lq[p];
            uint32_t doff = (uint32_t)(row * SA + q * 8) * 2;
            size_t ga = (rowA0 + row) * (size_t)K + (size_t)kt * 32 + q * 8;
            size_t gw = ((size_t)ncol0 + row) * (size_t)K + (size_t)kt * 32 + q * 8;
            cp16(base + 0 * TILEB * 2 + doff, Ah + ga);
            cp16(base + 1 * TILEB * 2 + doff, Al + ga);
            cp16(base + 2 * TILEB * 2 + doff, Wh + gw);
            cp16(base + 3 * TILEB * 2 + doff, Wl + gw);
        }
    };

    load_tile(0, 0);
    asm volatile("cp.async.commit_group;");

    // double-buffered fragment registers
    uint32_t fa[2][4][4], fb[2][4][2];

    for (int kt = 0; kt < nkt; kt++) {
        if (kt + 1 < nkt) {
            load_tile(kt + 1, (kt + 1) & 1);
            asm volatile("cp.async.commit_group;");
            asm volatile("cp.async.wait_group 1;");
        } else {
            asm volatile("cp.async.wait_group 0;");
        }
        __syncthreads();

        const uint32_t buf = smu + (uint32_t)(kt & 1) * BUFB * 2;

        // stage s = (combo, ks): combo = s>>1 in {AhWh, AhWl, AlWh}, ks = s&1
        auto load_frag = [&](int s, int fsel) {
            const int combo = s >> 1, ks = s & 1;
            const uint32_t Ab = buf + (combo == 2 ? 1 : 0) * TILEB * 2;
            const uint32_t Wb = buf + (combo == 1 ? 3 : 2) * TILEB * 2;
            const int kof = ks * 16 + 2 * t;
#pragma unroll
            for (int j = 0; j < 4; j++) {
                uint32_t nrow = (uint32_t)(wn * 32 + j * 8 + gg);
                uint32_t ad = Wb + (nrow * SA + kof) * 2;
                fb[fsel][j][0] = lds32(ad);
                fb[fsel][j][1] = lds32(ad + 16);
            }
#pragma unroll
            for (int i = 0; i < 4; i++) {
                uint32_t mrow = (uint32_t)(wm * 64 + i * 16 + gg);
                uint32_t ad = Ab + (mrow * SA + kof) * 2;
                fa[fsel][i][0] = lds32(ad);
                fa[fsel][i][1] = lds32(ad + SA * 8 * 2);
                fa[fsel][i][2] = lds32(ad + 16);
                fa[fsel][i][3] = lds32(ad + SA * 8 * 2 + 16);
            }
        };

        load_frag(0, 0);
#pragma unroll
        for (int s = 0; s < 6; s++) {
            if (s < 5) load_frag(s + 1, (s + 1) & 1);
            const int f = s & 1;
#pragma unroll
            for (int i = 0; i < 4; i++)
#pragma unroll
                for (int j = 0; j < 4; j++)
                    mma16816(c[i][j], fa[f][i][0], fa[f][i][1],
                             fa[f][i][2], fa[f][i][3],
                             fb[f][j][0], fb[f][j][1]);
        }
        __syncthreads();
    }

    // epilogue
#pragma unroll
    for (int i = 0; i < 4; i++) {
        size_t r0 = rowA0 + wm * 64 + i * 16 + gg;
        size_t r1 = r0 + 8;
#pragma unroll
        for (int j = 0; j < 4; j++) {
            int cl = wn * 32 + j * 8 + 2 * t;
            float b0v = sbias[cl], b1v = sbias[cl + 1];
            *(float2*)(C + r0 * G3 + ncol0 + cl) =
                make_float2(c[i][j][0] + b0v, c[i][j][1] + b1v);
            *(float2*)(C + r1 * G3 + ncol0 + cl) =
                make_float2(c[i][j][2] + b0v, c[i][j][3] + b1v);
        }
    }
}

// =======================================================================
// GRU sequential scan. 384 threads, one per gate output.
// 4 accumulator chains; gate threads compute r from their OWN dot
// before the barrier (r-row = rows 0..127); gates skip sh_g store.
// =======================================================================
__global__ __launch_bounds__(384, 1)
void gru_scan(const float* __restrict__ WhhF, const float* __restrict__ bhhF,
              const float* __restrict__ WhhB, const float* __restrict__ bhhB,
              int write_x1, int write_hN, int ndir)
{
    int bid = blockIdx.x;
    int dir, b;
    if (ndir == 2) { dir = bid >> 6; b = bid & 63; }
    else           { dir = 1;        b = bid; }

    const float* Whh = dir ? WhhB : WhhF;
    const float* bhh = dir ? bhhB : bhhF;
    const float* xp = g_xp + ((size_t)((ndir == 2) ? dir : 0) * B_ + b) * (size_t)T_ * G3;

    const int j = threadIdx.x;
    const bool is_gate = (j < H_);

    __shared__ __align__(16) float sh_h[H_];
    __shared__ float sh_g[G3];
    __shared__ float sh_xn[H_];

    unsigned long long w[H_ / 2];
    {
        const unsigned long long* wr =
            (const unsigned long long*)(Whh + (size_t)j * H_);
#pragma unroll
        for (int k = 0; k < H_ / 2; k++) w[k] = wr[k];
    }
    const float bj = bhh[j];
    if (is_gate) sh_h[j] = 0.f;
    float h_reg = 0.f;
    __syncthreads();

    const int t0 = dir ? (T_ - 1) : 0;
    const int dt = dir ? -1 : 1;
    const ulonglong2* h4 = (const ulonglong2*)sh_h;

    float xv0 = xp[(size_t)t0 * G3 + j];
    float xv1 = (T_ > 1) ? xp[(size_t)(t0 + dt) * G3 + j] : 0.f;

    for (int s = 0; s < T_; s++) {
        const int t = t0 + s * dt;
        float xv2 = 0.f;
        if (s + 2 < T_) xv2 = xp[(size_t)(t + 2 * dt) * G3 + j];

        unsigned long long a0 = 0ull, a1 = 0ull, a2 = 0ull, a3 = 0ull;
#pragma unroll
        for (int k = 0; k < H_ / 8; k++) {
            ulonglong2 hv0 = h4[2 * k];
            ulonglong2 hv1 = h4[2 * k + 1];
            a0 = ffma2(hv0.x, w[4 * k],     a0);
            a1 = ffma2(hv0.y, w[4 * k + 1], a1);
            a2 = ffma2(hv1.x, w[4 * k + 2], a2);
            a3 = ffma2(hv1.y, w[4 * k + 3], a3);
        }
        float2 p0 = u2f(a0), p1 = u2f(a1), p2 = u2f(a2), p3 = u2f(a3);
        float gsum = (p0.x + p0.y) + (p1.x + p1.y) +
                     (p2.x + p2.y) + (p3.x + p3.y) + bj;

        float r = 0.f;
        if (is_gate) {
            // own row is the r-row: compute r before the barrier
            r = sigmoid_fast(gsum + xv0);
            asm volatile("bar.sync 1, 384;" ::: "memory");
            float z  = sigmoid_fast(sh_g[H_ + j]);
            float n  = tanh_fast(sh_xn[j] + r * sh_g[2 * H_ + j]);
            float hn = (1.0f - z) * n + z * h_reg;
            h_reg = hn;
            sh_h[j] = hn;
            if (write_x1) {
                size_t idx = ((size_t)b * T_ + t) * (2 * H_) + (size_t)dir * H_ + j;
                __nv_bfloat16 hi = __float2bfloat16(hn);
                g_x1h[idx] = hi;
                g_x1l[idx] = __float2bfloat16(hn - __bfloat162float(hi));
            }
        } else {
            if (j < 2 * H_) { sh_g[j] = gsum + xv0; }
            else            { sh_g[j] = gsum; sh_xn[j - 2 * H_] = xv0; }
            asm volatile("bar.arrive 1, 384;" ::: "memory");
        }
        __syncthreads();
        xv0 = xv1;
        xv1 = xv2;
    }

    if (write_hN && is_gate) g_hN[b * H_ + j] = h_reg;
}

// =======================================================================
// Decoder
// =======================================================================
__device__ __forceinline__ float mishf(float x) {
    float sp = (x > 20.f) ? x : log1pf(expf(x));
    return x * tanhf(sp);
}
__device__ __forceinline__ float blockReduceSum(float v) {
#pragma unroll
    for (int o = 16; o > 0; o >>= 1) v += __shfl_xor_sync(0xffffffffu, v, o);
    __shared__ float s[4];
    int w = threadIdx.x >> 5;
    if ((threadIdx.x & 31) == 0) s[w] = v;
    __syncthreads();
    v = s[0] + s[1] + s[2] + s[3];
    __syncthreads();
    return v;
}

__global__ __launch_bounds__(128, 1)
void decoder(const float* __restrict__ g1, const float* __restrict__ be1,
             const float* __restrict__ W1, const float* __restrict__ b1,
             const float* __restrict__ g2, const float* __restrict__ be2,
             const float* __restrict__ W2, const float* __restrict__ b2,
             float* __restrict__ out)
{
    const int b = blockIdx.x, j = threadIdx.x;
    __shared__ float sv[H_];

    float v = mishf(g_hN[b * H_ + j]);
    float m = blockReduceSum(v) * (1.0f / H_);
    float d = v - m;
    float var = blockReduceSum(d * d) * (1.0f / H_);
    float y = d * rsqrtf(var + EPS_) * g1[j] + be1[j];
    sv[j] = y;
    __syncthreads();

    float t = b1[j];
#pragma unroll 4
    for (int k = 0; k < H_; k++) t = fmaf(sv[k], W1[j * H_ + k], t);
    float u = mishf(t);
    __syncthreads();

    m = blockReduceSum(u) * (1.0f / H_);
    d = u - m;
    var = blockReduceSum(d * d) * (1.0f / H_);
    float zz = d * rsqrtf(var + EPS_) * g2[j] + be2[j];

    float p = blockReduceSum(zz * W2[j]);
    if (j == 0) out[b] = p + b2[0];
}

// =======================================================================
// Host launcher
// =======================================================================
extern "C" void kernel_launch(void* const* d_in, const int* in_sizes, int n_in,
                              void* d_out, int out_size)
{
    (void)in_sizes; (void)n_in; (void)out_size;
    const float* x     = (const float*)d_in[0];
    const float* Wih0f = (const float*)d_in[1];
    const float* Whh0f = (const float*)d_in[2];
    const float* bih0f = (const float*)d_in[3];
    const float* bhh0f = (const float*)d_in[4];
    const float* Wih0b = (const float*)d_in[5];
    const float* Whh0b = (const float*)d_in[6];
    const float* bih0b = (const float*)d_in[7];
    const float* bhh0b = (const float*)d_in[8];
    // d_in[9..12] = layer-1 forward params: unused by the reference output
    const float* Wih1b = (const float*)d_in[13];
    const float* Whh1b = (const float*)d_in[14];
    const float* bih1b = (const float*)d_in[15];
    const float* bhh1b = (const float*)d_in[16];
    const float* g1  = (const float*)d_in[17];
    const float* be1 = (const float*)d_in[18];
    const float* W1  = (const float*)d_in[19];
    const float* b1  = (const float*)d_in[20];
    const float* g2  = (const float*)d_in[21];
    const float* be2 = (const float*)d_in[22];
    const float* W2  = (const float*)d_in[23];
    const float* b2  = (const float*)d_in[24];

    __nv_bfloat16 *xh, *xl, *w0fh, *w0fl, *w0bh, *w0bl, *w1bh, *w1bl, *x1h, *x1l;
    cudaGetSymbolAddress((void**)&xh,   g_xh);
    cudaGetSymbolAddress((void**)&xl,   g_xl);
    cudaGetSymbolAddress((void**)&w0fh, g_w0fh);
    cudaGetSymbolAddress((void**)&w0fl, g_w0fl);
    cudaGetSymbolAddress((void**)&w0bh, g_w0bh);
    cudaGetSymbolAddress((void**)&w0bl, g_w0bl);
    cudaGetSymbolAddress((void**)&w1bh, g_w1bh);
    cudaGetSymbolAddress((void**)&w1bl, g_w1bl);
    cudaGetSymbolAddress((void**)&x1h,  g_x1h);
    cudaGetSymbolAddress((void**)&x1l,  g_x1l);

    static int smem_set = 0;
    if (!smem_set) {
        cudaFuncSetAttribute(hmma_gemm,
                             cudaFuncAttributeMaxDynamicSharedMemorySize, HG_SMEM);
        smem_set = 1;
    }

    // split inputs into bf16 hi/lo
    split_bf16<<<4096, 256>>>(x, xh, xl, (size_t)MTOT * IN_);
    split_bf16<<<64, 256>>>(Wih0f, w0fh, w0fl, (size_t)G3 * IN_);
    split_bf16<<<64, 256>>>(Wih0b, w0bh, w0bl, (size_t)G3 * IN_);
    split_bf16<<<32, 256>>>(Wih1b, w1bh, w1bl, (size_t)G3 * 2 * H_);

    // layer-0 projections: grid (n-tile, m-tile, dir) — n fastest for A L2 reuse
    {
        dim3 grid(3, MTOT / 128, 2);
        hmma_gemm<<<grid, 256, HG_SMEM>>>(xh, xl, IN_,
                                          w0fh, w0fl, bih0f,
                                          w0bh, w0bl, bih0b);
    }
    gru_scan<<<128, 384>>>(Whh0f, bhh0f, Whh0b, bhh0b, 1, 0, 2);
    // layer-1 backward projection
    {
        dim3 grid(3, MTOT / 128, 1);
        hmma_gemm<<<grid, 256, HG_SMEM>>>(x1h, x1l, 2 * H_,
                                          w1bh, w1bl, bih1b,
                                          w1bh, w1bl, bih1b);
    }
    gru_scan<<<64, 384>>>(Whh1b, bhh1b, Whh1b, bhh1b, 0, 1, 1);
    decoder<<<64, 128>>>(g1, be1, W1, b1, g2, be2, W2, b2, (float*)d_out);
}

// round 10
// speedup vs baseline: 2.0025x; 1.0220x over previous
#include <cuda_runtime.h>
#include <cuda_bf16.h>
#include <math.h>
#include <stdint.h>

// Problem dims
#define B_   64
#define T_   2048
#define IN_  512
#define H_   128
#define G3   384            // 3*H
#define EPS_ 1e-5f
#define MTOT (B_ * T_)      // 131072

// ---------------- device scratch ----------------
__device__ float g_xp[(size_t)2 * B_ * T_ * G3];              // [dir][B][T][3H] fp32
__device__ __nv_bfloat16 g_xh[(size_t)MTOT * IN_];
__device__ __nv_bfloat16 g_xl[(size_t)MTOT * IN_];
__device__ __nv_bfloat16 g_x1h[(size_t)MTOT * 2 * H_];
__device__ __nv_bfloat16 g_x1l[(size_t)MTOT * 2 * H_];
__device__ __nv_bfloat16 g_w0fh[G3 * IN_], g_w0fl[G3 * IN_];
__device__ __nv_bfloat16 g_w0bh[G3 * IN_], g_w0bl[G3 * IN_];
__device__ __nv_bfloat16 g_w1bh[G3 * 2 * H_], g_w1bl[G3 * 2 * H_];
__device__ float g_hN[B_ * H_];

// ---------------- helpers ----------------
__device__ __forceinline__ unsigned long long ffma2(unsigned long long a,
                                                    unsigned long long b,
                                                    unsigned long long c) {
    unsigned long long d;
    asm("fma.rn.f32x2 %0, %1, %2, %3;" : "=l"(d) : "l"(a), "l"(b), "l"(c));
    return d;
}
__device__ __forceinline__ float2 u2f(unsigned long long u) {
    float2 f;
    asm("mov.b64 {%0, %1}, %2;" : "=f"(f.x), "=f"(f.y) : "l"(u));
    return f;
}
__device__ __forceinline__ float tanh_fast(float x) {
    float y;
    asm("tanh.approx.f32 %0, %1;" : "=f"(y) : "f"(x));
    return y;
}
__device__ __forceinline__ float sigmoid_fast(float x) {
    return fmaf(0.5f, tanh_fast(0.5f * x), 0.5f);
}
__device__ __forceinline__ void cp16(uint32_t dst, const void* src) {
    asm volatile("cp.async.cg.shared.global [%0], [%1], 16;" :: "r"(dst), "l"(src));
}
__device__ __forceinline__ uint32_t s2u(const void* p) {
    uint32_t a;
    asm("{ .reg .u64 t; cvta.to.shared.u64 t, %1; cvt.u32.u64 %0, t; }"
        : "=r"(a) : "l"(p));
    return a;
}
__device__ __forceinline__ void ldsm4(uint32_t& r0, uint32_t& r1,
                                      uint32_t& r2, uint32_t& r3, uint32_t a) {
    asm volatile("ldmatrix.sync.aligned.m8n8.x4.shared.b16 {%0,%1,%2,%3}, [%4];"
                 : "=r"(r0), "=r"(r1), "=r"(r2), "=r"(r3) : "r"(a));
}
__device__ __forceinline__ void mma16816(float* c, uint32_t a0, uint32_t a1,
                                         uint32_t a2, uint32_t a3,
                                         uint32_t b0, uint32_t b1) {
    asm volatile(
        "mma.sync.aligned.m16n8k16.row.col.f32.bf16.bf16.f32 "
        "{%0,%1,%2,%3}, {%4,%5,%6,%7}, {%8,%9}, {%0,%1,%2,%3};"
        : "+f"(c[0]), "+f"(c[1]), "+f"(c[2]), "+f"(c[3])
        : "r"(a0), "r"(a1), "r"(a2), "r"(a3), "r"(b0), "r"(b1));
}

// =======================================================================
// Split fp32 -> bf16 (hi, lo)
// =======================================================================
__global__ void split_bf16(const float* __restrict__ src,
                           __nv_bfloat16* __restrict__ dh,
                           __nv_bfloat16* __restrict__ dl, size_t n)
{
    size_t i = ((size_t)blockIdx.x * blockDim.x + threadIdx.x) * 4;
    size_t stride = (size_t)gridDim.x * blockDim.x * 4;
    for (; i < n; i += stride) {
        float4 v = *(const float4*)(src + i);
        __nv_bfloat16 h0 = __float2bfloat16(v.x);
        __nv_bfloat16 h1 = __float2bfloat16(v.y);
        __nv_bfloat16 h2 = __float2bfloat16(v.z);
        __nv_bfloat16 h3 = __float2bfloat16(v.w);
        __nv_bfloat16 l0 = __float2bfloat16(v.x - __bfloat162float(h0));
        __nv_bfloat16 l1 = __float2bfloat16(v.y - __bfloat162float(h1));
        __nv_bfloat16 l2 = __float2bfloat16(v.z - __bfloat162float(h2));
        __nv_bfloat16 l3 = __float2bfloat16(v.w - __bfloat162float(h3));
        *(__nv_bfloat162*)(dh + i)     = __nv_bfloat162(h0, h1);
        *(__nv_bfloat162*)(dh + i + 2) = __nv_bfloat162(h2, h3);
        *(__nv_bfloat162*)(dl + i)     = __nv_bfloat162(l0, l1);
        *(__nv_bfloat162*)(dl + i + 2) = __nv_bfloat162(l2, l3);
    }
}

// =======================================================================
// HMMA split-bf16 GEMM, fragments via ldmatrix (6 LDSM/stage vs 24 LDS).
// CTA: 128(M) x 128(N), 8 warps (2m x 4n), warp tile m64n32.
// grid: (n-tile=3 fastest, m-tile, dir) -> A tile L2 reuse.
// =======================================================================
#define SA 40                 // padded row stride in bf16 (80B rows, LDSM bank-clean)
#define TILEB (128 * SA)
#define BUFB  (4 * TILEB)     // Ah,Al,Wh,Wl
#define HG_SMEM (2 * BUFB * 2 + 512)

__global__ __launch_bounds__(256, 2)
void hmma_gemm(const __nv_bfloat16* __restrict__ Ah,
               const __nv_bfloat16* __restrict__ Al, int K,
               const __nv_bfloat16* __restrict__ Wh0,
               const __nv_bfloat16* __restrict__ Wl0, const float* __restrict__ b0,
               const __nv_bfloat16* __restrict__ Wh1,
               const __nv_bfloat16* __restrict__ Wl1, const float* __restrict__ b1)
{
    extern __shared__ __nv_bfloat16 sm[];
    const __nv_bfloat16* Wh = blockIdx.z ? Wh1 : Wh0;
    const __nv_bfloat16* Wl = blockIdx.z ? Wl1 : Wl0;
    const float* bias = blockIdx.z ? b1 : b0;
    float* C = g_xp + (size_t)blockIdx.z * MTOT * G3;

    float* sbias = (float*)(sm + 2 * BUFB);
    const uint32_t smu = s2u(sm);

    const int tid  = threadIdx.x;
    const int wid  = tid >> 5;
    const int lane = tid & 31;
    const int wm   = wid >> 2;
    const int wn   = wid & 3;
    const int gg   = lane >> 2;          // 0..7  (epilogue row)
    const int t    = lane & 3;           // 0..3  (epilogue col pair)
    const int rrow = lane & 7;           // ldmatrix row within group
    const int grp  = lane >> 3;          // ldmatrix address group 0..3

    const size_t rowA0 = (size_t)blockIdx.y * 128;
    const int    ncol0 = blockIdx.x * 128;

    if (tid < 128) sbias[tid] = bias[ncol0 + tid];

    int lrow[2], lq[2];
#pragma unroll
    for (int p = 0; p < 2; p++) {
        int u = p * 256 + tid;
        lrow[p] = u >> 2;
        lq[p]   = u & 3;
    }

    float c[4][4][4];
#pragma unroll
    for (int i = 0; i < 4; i++)
#pragma unroll
        for (int j = 0; j < 4; j++)
#pragma unroll
            for (int q = 0; q < 4; q++) c[i][j][q] = 0.f;

    const int nkt = K / 32;

    auto load_tile = [&](int kt, int b) {
        uint32_t base = smu + (uint32_t)b * BUFB * 2;
#pragma unroll
        for (int p = 0; p < 2; p++) {
            int row = lrow[p], q = lq[p];
            uint32_t doff = (uint32_t)(row * SA + q * 8) * 2;
            size_t ga = (rowA0 + row) * (size_t)K + (size_t)kt * 32 + q * 8;
            size_t gw = ((size_t)ncol0 + row) * (size_t)K + (size_t)kt * 32 + q * 8;
            cp16(base + 0 * TILEB * 2 + doff, Ah + ga);
            cp16(base + 1 * TILEB * 2 + doff, Al + ga);
            cp16(base + 2 * TILEB * 2 + doff, Wh + gw);
            cp16(base + 3 * TILEB * 2 + doff, Wl + gw);
        }
    };

    load_tile(0, 0);
    asm volatile("cp.async.commit_group;");

    // ldmatrix per-lane base offsets (elements, within a tile array)
    // A tile i: row = wm*64 + i*16 + rrow + (grp&1)*8 ; k = kof + (grp>>1)*8
    const uint32_t a_lane = (uint32_t)((wm * 64 + rrow + (grp & 1) * 8) * SA + (grp >> 1) * 8);
    // B pair jj (subtiles 2jj, 2jj+1): n = wn*32 + (2jj + (grp>>1))*8 + rrow ; k = kof + (grp&1)*8
    const uint32_t b_lane = (uint32_t)((wn * 32 + (grp >> 1) * 8 + rrow) * SA + (grp & 1) * 8);

    for (int kt = 0; kt < nkt; kt++) {
        if (kt + 1 < nkt) {
            load_tile(kt + 1, (kt + 1) & 1);
            asm volatile("cp.async.commit_group;");
            asm volatile("cp.async.wait_group 1;");
        } else {
            asm volatile("cp.async.wait_group 0;");
        }
        __syncthreads();

        const uint32_t buf = smu + (uint32_t)(kt & 1) * BUFB * 2;

        // stage s = (combo, ks): combo in {AhWh, AhWl, AlWh}
#pragma unroll
        for (int s = 0; s < 6; s++) {
            const int combo = s >> 1, ks = s & 1;
            const uint32_t Ab = buf + (combo == 2 ? 1 : 0) * TILEB * 2;
            const uint32_t Wb = buf + (combo == 1 ? 3 : 2) * TILEB * 2;
            const uint32_t kof2 = (uint32_t)(ks * 16) * 2;   // bytes

            uint32_t fb[4][2];
#pragma unroll
            for (int jj = 0; jj < 2; jj++) {
                uint32_t ad = Wb + (b_lane + (uint32_t)(jj * 16 * SA)) * 2 + kof2;
                ldsm4(fb[2 * jj][0], fb[2 * jj][1],
                      fb[2 * jj + 1][0], fb[2 * jj + 1][1], ad);
            }
            uint32_t fa[4][4];
#pragma unroll
            for (int i = 0; i < 4; i++) {
                uint32_t ad = Ab + (a_lane + (uint32_t)(i * 16 * SA)) * 2 + kof2;
                ldsm4(fa[i][0], fa[i][1], fa[i][2], fa[i][3], ad);
            }
#pragma unroll
            for (int i = 0; i < 4; i++)
#pragma unroll
                for (int j = 0; j < 4; j++)
                    mma16816(c[i][j], fa[i][0], fa[i][1], fa[i][2], fa[i][3],
                             fb[j][0], fb[j][1]);
        }
        __syncthreads();
    }

    // epilogue
#pragma unroll
    for (int i = 0; i < 4; i++) {
        size_t r0 = rowA0 + wm * 64 + i * 16 + gg;
        size_t r1 = r0 + 8;
#pragma unroll
        for (int j = 0; j < 4; j++) {
            int cl = wn * 32 + j * 8 + 2 * t;
            float b0v = sbias[cl], b1v = sbias[cl + 1];
            *(float2*)(C + r0 * G3 + ncol0 + cl) =
                make_float2(c[i][j][0] + b0v, c[i][j][1] + b1v);
            *(float2*)(C + r1 * G3 + ncol0 + cl) =
                make_float2(c[i][j][2] + b0v, c[i][j][3] + b1v);
        }
    }
}

// =======================================================================
// GRU sequential scan. 384 threads, one per gate output.
// r computed by gate rows pre-barrier; z computed by z-rows pre-barrier
// (sh_g[H+j] holds sigmoid already). n-rows store raw gsum + xn.
// =======================================================================
__global__ __launch_bounds__(384, 1)
void gru_scan(const float* __restrict__ WhhF, const float* __restrict__ bhhF,
              const float* __restrict__ WhhB, const float* __restrict__ bhhB,
              int write_x1, int write_hN, int ndir)
{
    int bid = blockIdx.x;
    int dir, b;
    if (ndir == 2) { dir = bid >> 6; b = bid & 63; }
    else           { dir = 1;        b = bid; }

    const float* Whh = dir ? WhhB : WhhF;
    const float* bhh = dir ? bhhB : bhhF;
    const float* xp = g_xp + ((size_t)((ndir == 2) ? dir : 0) * B_ + b) * (size_t)T_ * G3;

    const int j = threadIdx.x;
    const bool is_gate = (j < H_);
    const bool is_z    = (j >= H_ && j < 2 * H_);

    __shared__ __align__(16) float sh_h[H_];
    __shared__ float sh_g[G3];
    __shared__ float sh_xn[H_];

    unsigned long long w[H_ / 2];
    {
        const unsigned long long* wr =
            (const unsigned long long*)(Whh + (size_t)j * H_);
#pragma unroll
        for (int k = 0; k < H_ / 2; k++) w[k] = wr[k];
    }
    const float bj = bhh[j];
    if (is_gate) sh_h[j] = 0.f;
    float h_reg = 0.f;
    __syncthreads();

    const int t0 = dir ? (T_ - 1) : 0;
    const int dt = dir ? -1 : 1;
    const ulonglong2* h4 = (const ulonglong2*)sh_h;

    float xv0 = xp[(size_t)t0 * G3 + j];
    float xv1 = (T_ > 1) ? xp[(size_t)(t0 + dt) * G3 + j] : 0.f;

    for (int s = 0; s < T_; s++) {
        const int t = t0 + s * dt;
        float xv2 = 0.f;
        if (s + 2 < T_) xv2 = xp[(size_t)(t + 2 * dt) * G3 + j];

        unsigned long long a0 = 0ull, a1 = 0ull, a2 = 0ull, a3 = 0ull;
#pragma unroll
        for (int k = 0; k < H_ / 8; k++) {
            ulonglong2 hv0 = h4[2 * k];
            ulonglong2 hv1 = h4[2 * k + 1];
            a0 = ffma2(hv0.x, w[4 * k],     a0);
            a1 = ffma2(hv0.y, w[4 * k + 1], a1);
            a2 = ffma2(hv1.x, w[4 * k + 2], a2);
            a3 = ffma2(hv1.y, w[4 * k + 3], a3);
        }
        float2 p0 = u2f(a0), p1 = u2f(a1), p2 = u2f(a2), p3 = u2f(a3);
        float gsum = (p0.x + p0.y) + (p1.x + p1.y) +
                     (p2.x + p2.y) + (p3.x + p3.y) + bj;

        if (is_gate) {
            float r = sigmoid_fast(gsum + xv0);      // own row = r-row
            asm volatile("bar.sync 1, 384;" ::: "memory");
            float z  = sh_g[H_ + j];                 // already sigmoided
            float n  = tanh_fast(sh_xn[j] + r * sh_g[2 * H_ + j]);
            float hn = (1.0f - z) * n + z * h_reg;
            h_reg = hn;
            sh_h[j] = hn;
            if (write_x1) {
                size_t idx = ((size_t)b * T_ + t) * (2 * H_) + (size_t)dir * H_ + j;
                __nv_bfloat16 hi = __float2bfloat16(hn);
                g_x1h[idx] = hi;
                g_x1l[idx] = __float2bfloat16(hn - __bfloat162float(hi));
            }
        } else {
            if (is_z) { sh_g[j] = sigmoid_fast(gsum + xv0); }
            else      { sh_g[j] = gsum; sh_xn[j - 2 * H_] = xv0; }
            asm volatile("bar.arrive 1, 384;" ::: "memory");
        }
        __syncthreads();
        xv0 = xv1;
        xv1 = xv2;
    }

    if (write_hN && is_gate) g_hN[b * H_ + j] = h_reg;
}

// =======================================================================
// Decoder
// =======================================================================
__device__ __forceinline__ float mishf(float x) {
    float sp = (x > 20.f) ? x : log1pf(expf(x));
    return x * tanhf(sp);
}
__device__ __forceinline__ float blockReduceSum(float v) {
#pragma unroll
    for (int o = 16; o > 0; o >>= 1) v += __shfl_xor_sync(0xffffffffu, v, o);
    __shared__ float s[4];
    int w = threadIdx.x >> 5;
    if ((threadIdx.x & 31) == 0) s[w] = v;
    __syncthreads();
    v = s[0] + s[1] + s[2] + s[3];
    __syncthreads();
    return v;
}

__global__ __launch_bounds__(128, 1)
void decoder(const float* __restrict__ g1, const float* __restrict__ be1,
             const float* __restrict__ W1, const float* __restrict__ b1,
             const float* __restrict__ g2, const float* __restrict__ be2,
             const float* __restrict__ W2, const float* __restrict__ b2,
             float* __restrict__ out)
{
    const int b = blockIdx.x, j = threadIdx.x;
    __shared__ float sv[H_];

    float v = mishf(g_hN[b * H_ + j]);
    float m = blockReduceSum(v) * (1.0f / H_);
    float d = v - m;
    float var = blockReduceSum(d * d) * (1.0f / H_);
    float y = d * rsqrtf(var + EPS_) * g1[j] + be1[j];
    sv[j] = y;
    __syncthreads();

    float t = b1[j];
#pragma unroll 4
    for (int k = 0; k < H_; k++) t = fmaf(sv[k], W1[j * H_ + k], t);
    float u = mishf(t);
    __syncthreads();

    m = blockReduceSum(u) * (1.0f / H_);
    d = u - m;
    var = blockReduceSum(d * d) * (1.0f / H_);
    float zz = d * rsqrtf(var + EPS_) * g2[j] + be2[j];

    float p = blockReduceSum(zz * W2[j]);
    if (j == 0) out[b] = p + b2[0];
}

// =======================================================================
// Host launcher
// =======================================================================
extern "C" void kernel_launch(void* const* d_in, const int* in_sizes, int n_in,
                              void* d_out, int out_size)
{
    (void)in_sizes; (void)n_in; (void)out_size;
    const float* x     = (const float*)d_in[0];
    const float* Wih0f = (const float*)d_in[1];
    const float* Whh0f = (const float*)d_in[2];
    const float* bih0f = (const float*)d_in[3];
    const float* bhh0f = (const float*)d_in[4];
    const float* Wih0b = (const float*)d_in[5];
    const float* Whh0b = (const float*)d_in[6];
    const float* bih0b = (const float*)d_in[7];
    const float* bhh0b = (const float*)d_in[8];
    // d_in[9..12] = layer-1 forward params: unused by the reference output
    const float* Wih1b = (const float*)d_in[13];
    const float* Whh1b = (const float*)d_in[14];
    const float* bih1b = (const float*)d_in[15];
    const float* bhh1b = (const float*)d_in[16];
    const float* g1  = (const float*)d_in[17];
    const float* be1 = (const float*)d_in[18];
    const float* W1  = (const float*)d_in[19];
    const float* b1  = (const float*)d_in[20];
    const float* g2  = (const float*)d_in[21];
    const float* be2 = (const float*)d_in[22];
    const float* W2  = (const float*)d_in[23];
    const float* b2  = (const float*)d_in[24];

    __nv_bfloat16 *xh, *xl, *w0fh, *w0fl, *w0bh, *w0bl, *w1bh, *w1bl, *x1h, *x1l;
    cudaGetSymbolAddress((void**)&xh,   g_xh);
    cudaGetSymbolAddress((void**)&xl,   g_xl);
    cudaGetSymbolAddress((void**)&w0fh, g_w0fh);
    cudaGetSymbolAddress((void**)&w0fl, g_w0fl);
    cudaGetSymbolAddress((void**)&w0bh, g_w0bh);
    cudaGetSymbolAddress((void**)&w0bl, g_w0bl);
    cudaGetSymbolAddress((void**)&w1bh, g_w1bh);
    cudaGetSymbolAddress((void**)&w1bl, g_w1bl);
    cudaGetSymbolAddress((void**)&x1h,  g_x1h);
    cudaGetSymbolAddress((void**)&x1l,  g_x1l);

    static int smem_set = 0;
    if (!smem_set) {
        cudaFuncSetAttribute(hmma_gemm,
                             cudaFuncAttributeMaxDynamicSharedMemorySize, HG_SMEM);
        smem_set = 1;
    }

    // split inputs into bf16 hi/lo
    split_bf16<<<4096, 256>>>(x, xh, xl, (size_t)MTOT * IN_);
    split_bf16<<<64, 256>>>(Wih0f, w0fh, w0fl, (size_t)G3 * IN_);
    split_bf16<<<64, 256>>>(Wih0b, w0bh, w0bl, (size_t)G3 * IN_);
    split_bf16<<<32, 256>>>(Wih1b, w1bh, w1bl, (size_t)G3 * 2 * H_);

    // layer-0 projections: grid (n-tile, m-tile, dir) — n fastest for A L2 reuse
    {
        dim3 grid(3, MTOT / 128, 2);
        hmma_gemm<<<grid, 256, HG_SMEM>>>(xh, xl, IN_,
                                          w0fh, w0fl, bih0f,
                                          w0bh, w0bl, bih0b);
    }
    gru_scan<<<128, 384>>>(Whh0f, bhh0f, Whh0b, bhh0b, 1, 0, 2);
    // layer-1 backward projection
    {
        dim3 grid(3, MTOT / 128, 1);
        hmma_gemm<<<grid, 256, HG_SMEM>>>(x1h, x1l, 2 * H_,
                                          w1bh, w1bl, bih1b,
                                          w1bh, w1bl, bih1b);
    }
    gru_scan<<<64, 384>>>(Whh1b, bhh1b, Whh1b, bhh1b, 0, 1, 1);
    decoder<<<64, 128>>>(g1, be1, W1, b1, g2, be2, W2, b2, (float*)d_out);
}

// round 14
// speedup vs baseline: 2.0375x; 1.0175x over previous
#include <cuda_runtime.h>
#include <cuda_bf16.h>
#include <math.h>
#include <stdint.h>

// Problem dims
#define B_   64
#define T_   2048
#define IN_  512
#define H_   128
#define G3   384            // 3*H
#define EPS_ 1e-5f
#define MTOT (B_ * T_)      // 131072

// ---------------- device scratch ----------------
__device__ float g_xp[(size_t)2 * B_ * T_ * G3];              // [dir][B][T][3H] fp32
__device__ __nv_bfloat16 g_xh[(size_t)MTOT * IN_];
__device__ __nv_bfloat16 g_xl[(size_t)MTOT * IN_];
__device__ __nv_bfloat16 g_x1h[(size_t)MTOT * 2 * H_];
__device__ __nv_bfloat16 g_x1l[(size_t)MTOT * 2 * H_];
__device__ __nv_bfloat16 g_w0fh[G3 * IN_], g_w0fl[G3 * IN_];
__device__ __nv_bfloat16 g_w0bh[G3 * IN_], g_w0bl[G3 * IN_];
__device__ __nv_bfloat16 g_w1bh[G3 * 2 * H_], g_w1bl[G3 * 2 * H_];
__device__ float g_hN[B_ * H_];

// ---------------- helpers ----------------
__device__ __forceinline__ unsigned long long ffma2(unsigned long long a,
                                                    unsigned long long b,
                                                    unsigned long long c) {
    unsigned long long d;
    asm("fma.rn.f32x2 %0, %1, %2, %3;" : "=l"(d) : "l"(a), "l"(b), "l"(c));
    return d;
}
__device__ __forceinline__ float2 u2f(unsigned long long u) {
    float2 f;
    asm("mov.b64 {%0, %1}, %2;" : "=f"(f.x), "=f"(f.y) : "l"(u));
    return f;
}
__device__ __forceinline__ float tanh_fast(float x) {
    float y;
    asm("tanh.approx.f32 %0, %1;" : "=f"(y) : "f"(x));
    return y;
}
__device__ __forceinline__ float sigmoid_fast(float x) {
    return fmaf(0.5f, tanh_fast(0.5f * x), 0.5f);
}
__device__ __forceinline__ void cp16(uint32_t dst, const void* src) {
    asm volatile("cp.async.cg.shared.global [%0], [%1], 16;" :: "r"(dst), "l"(src));
}
__device__ __forceinline__ uint32_t s2u(const void* p) {
    uint32_t a;
    asm("{ .reg .u64 t; cvta.to.shared.u64 t, %1; cvt.u32.u64 %0, t; }"
        : "=r"(a) : "l"(p));
    return a;
}
__device__ __forceinline__ void ldsm4(uint32_t& r0, uint32_t& r1,
                                      uint32_t& r2, uint32_t& r3, uint32_t a) {
    asm volatile("ldmatrix.sync.aligned.m8n8.x4.shared.b16 {%0,%1,%2,%3}, [%4];"
                 : "=r"(r0), "=r"(r1), "=r"(r2), "=r"(r3) : "r"(a));
}
__device__ __forceinline__ void mma16816(float* c, uint32_t a0, uint32_t a1,
                                         uint32_t a2, uint32_t a3,
                                         uint32_t b0, uint32_t b1) {
    asm volatile(
        "mma.sync.aligned.m16n8k16.row.col.f32.bf16.bf16.f32 "
        "{%0,%1,%2,%3}, {%4,%5,%6,%7}, {%8,%9}, {%0,%1,%2,%3};"
        : "+f"(c[0]), "+f"(c[1]), "+f"(c[2]), "+f"(c[3])
        : "r"(a0), "r"(a1), "r"(a2), "r"(a3), "r"(b0), "r"(b1));
}

// =======================================================================
// Split fp32 -> bf16 (hi, lo)
// =======================================================================
__global__ void split_bf16(const float* __restrict__ src,
                           __nv_bfloat16* __restrict__ dh,
                           __nv_bfloat16* __restrict__ dl, size_t n)
{
    size_t i = ((size_t)blockIdx.x * blockDim.x + threadIdx.x) * 4;
    size_t stride = (size_t)gridDim.x * blockDim.x * 4;
    for (; i < n; i += stride) {
        float4 v = *(const float4*)(src + i);
        __nv_bfloat16 h0 = __float2bfloat16(v.x);
        __nv_bfloat16 h1 = __float2bfloat16(v.y);
        __nv_bfloat16 h2 = __float2bfloat16(v.z);
        __nv_bfloat16 h3 = __float2bfloat16(v.w);
        __nv_bfloat16 l0 = __float2bfloat16(v.x - __bfloat162float(h0));
        __nv_bfloat16 l1 = __float2bfloat16(v.y - __bfloat162float(h1));
        __nv_bfloat16 l2 = __float2bfloat16(v.z - __bfloat162float(h2));
        __nv_bfloat16 l3 = __float2bfloat16(v.w - __bfloat162float(h3));
        *(__nv_bfloat162*)(dh + i)     = __nv_bfloat162(h0, h1);
        *(__nv_bfloat162*)(dh + i + 2) = __nv_bfloat162(h2, h3);
        *(__nv_bfloat162*)(dl + i)     = __nv_bfloat162(l0, l1);
        *(__nv_bfloat162*)(dl + i + 2) = __nv_bfloat162(l2, l3);
    }
}

// =======================================================================
// HMMA split-bf16 GEMM, fragments via ldmatrix (verified R10 version).
// CTA: 128(M) x 128(N), 8 warps (2m x 4n), warp tile m64n32.
// grid: (n-tile=3 fastest, m-tile, dir) -> A tile L2 reuse.
// =======================================================================
#define SA 40                 // padded row stride in bf16 (80B rows, LDSM bank-clean)
#define TILEB (128 * SA)
#define BUFB  (4 * TILEB)     // Ah,Al,Wh,Wl
#define HG_SMEM (2 * BUFB * 2 + 512)

__global__ __launch_bounds__(256, 2)
void hmma_gemm(const __nv_bfloat16* __restrict__ Ah,
               const __nv_bfloat16* __restrict__ Al, int K,
               const __nv_bfloat16* __restrict__ Wh0,
               const __nv_bfloat16* __restrict__ Wl0, const float* __restrict__ b0,
               const __nv_bfloat16* __restrict__ Wh1,
               const __nv_bfloat16* __restrict__ Wl1, const float* __restrict__ b1)
{
    extern __shared__ __nv_bfloat16 sm[];
    const __nv_bfloat16* Wh = blockIdx.z ? Wh1 : Wh0;
    const __nv_bfloat16* Wl = blockIdx.z ? Wl1 : Wl0;
    const float* bias = blockIdx.z ? b1 : b0;
    float* C = g_xp + (size_t)blockIdx.z * MTOT * G3;

    float* sbias = (float*)(sm + 2 * BUFB);
    const uint32_t smu = s2u(sm);

    const int tid  = threadIdx.x;
    const int wid  = tid >> 5;
    const int lane = tid & 31;
    const int wm   = wid >> 2;
    const int wn   = wid & 3;
    const int gg   = lane >> 2;          // 0..7  (epilogue row)
    const int t    = lane & 3;           // 0..3  (epilogue col pair)
    const int rrow = lane & 7;           // ldmatrix row within group
    const int grp  = lane >> 3;          // ldmatrix address group 0..3

    const size_t rowA0 = (size_t)blockIdx.y * 128;
    const int    ncol0 = blockIdx.x * 128;

    if (tid < 128) sbias[tid] = bias[ncol0 + tid];

    int lrow[2], lq[2];
#pragma unroll
    for (int p = 0; p < 2; p++) {
        int u = p * 256 + tid;
        lrow[p] = u >> 2;
        lq[p]   = u & 3;
    }

    float c[4][4][4];
#pragma unroll
    for (int i = 0; i < 4; i++)
#pragma unroll
        for (int j = 0; j < 4; j++)
#pragma unroll
            for (int q = 0; q < 4; q++) c[i][j][q] = 0.f;

    const int nkt = K / 32;

    auto load_tile = [&](int kt, int b) {
        uint32_t base = smu + (uint32_t)b * BUFB * 2;
#pragma unroll
        for (int p = 0; p < 2; p++) {
            int row = lrow[p], q = lq[p];
            uint32_t doff = (uint32_t)(row * SA + q * 8) * 2;
            size_t ga = (rowA0 + row) * (size_t)K + (size_t)kt * 32 + q * 8;
            size_t gw = ((size_t)ncol0 + row) * (size_t)K + (size_t)kt * 32 + q * 8;
            cp16(base + 0 * TILEB * 2 + doff, Ah + ga);
            cp16(base + 1 * TILEB * 2 + doff, Al + ga);
            cp16(base + 2 * TILEB * 2 + doff, Wh + gw);
            cp16(base + 3 * TILEB * 2 + doff, Wl + gw);
        }
    };

    load_tile(0, 0);
    asm volatile("cp.async.commit_group;");

    // ldmatrix per-lane base offsets (elements, within a tile array)
    const uint32_t a_lane = (uint32_t)((wm * 64 + rrow + (grp & 1) * 8) * SA + (grp >> 1) * 8);
    const uint32_t b_lane = (uint32_t)((wn * 32 + (grp >> 1) * 8 + rrow) * SA + (grp & 1) * 8);

    for (int kt = 0; kt < nkt; kt++) {
        if (kt + 1 < nkt) {
            load_tile(kt + 1, (kt + 1) & 1);
            asm volatile("cp.async.commit_group;");
            asm volatile("cp.async.wait_group 1;");
        } else {
            asm volatile("cp.async.wait_group 0;");
        }
        __syncthreads();

        const uint32_t buf = smu + (uint32_t)(kt & 1) * BUFB * 2;

        // stage s = (combo, ks): combo in {AhWh, AhWl, AlWh}
#pragma unroll
        for (int s = 0; s < 6; s++) {
            const int combo = s >> 1, ks = s & 1;
            const uint32_t Ab = buf + (combo == 2 ? 1 : 0) * TILEB * 2;
            const uint32_t Wb = buf + (combo == 1 ? 3 : 2) * TILEB * 2;
            const uint32_t kof2 = (uint32_t)(ks * 16) * 2;   // bytes

            uint32_t fb[4][2];
#pragma unroll
            for (int jj = 0; jj < 2; jj++) {
                uint32_t ad = Wb + (b_lane + (uint32_t)(jj * 16 * SA)) * 2 + kof2;
                ldsm4(fb[2 * jj][0], fb[2 * jj][1],
                      fb[2 * jj + 1][0], fb[2 * jj + 1][1], ad);
            }
            uint32_t fa[4][4];
#pragma unroll
            for (int i = 0; i < 4; i++) {
                uint32_t ad = Ab + (a_lane + (uint32_t)(i * 16 * SA)) * 2 + kof2;
                ldsm4(fa[i][0], fa[i][1], fa[i][2], fa[i][3], ad);
            }
#pragma unroll
            for (int i = 0; i < 4; i++)
#pragma unroll
                for (int j = 0; j < 4; j++)
                    mma16816(c[i][j], fa[i][0], fa[i][1], fa[i][2], fa[i][3],
                             fb[j][0], fb[j][1]);
        }
        __syncthreads();
    }

    // epilogue
#pragma unroll
    for (int i = 0; i < 4; i++) {
        size_t r0 = rowA0 + wm * 64 + i * 16 + gg;
        size_t r1 = r0 + 8;
#pragma unroll
        for (int j = 0; j < 4; j++) {
            int cl = wn * 32 + j * 8 + 2 * t;
            float b0v = sbias[cl], b1v = sbias[cl + 1];
            *(float2*)(C + r0 * G3 + ncol0 + cl) =
                make_float2(c[i][j][0] + b0v, c[i][j][1] + b1v);
            *(float2*)(C + r1 * G3 + ncol0 + cl) =
                make_float2(c[i][j][2] + b0v, c[i][j][3] + b1v);
        }
    }
}

// =======================================================================
// GRU sequential scan. 384 threads, one per gate output.
// r computed by gate rows pre-barrier; z rows store sigmoid pre-barrier.
// NEW: x1 bf16 split+store DEFERRED one step — issued at the top of the
// next iteration so CVT/STG overlap the FFMA dot chain instead of
// sitting in the inter-barrier critical path.
// =======================================================================
__global__ __launch_bounds__(384, 1)
void gru_scan(const float* __restrict__ WhhF, const float* __restrict__ bhhF,
              const float* __restrict__ WhhB, const float* __restrict__ bhhB,
              int write_x1, int write_hN, int ndir)
{
    int bid = blockIdx.x;
    int dir, b;
    if (ndir == 2) { dir = bid >> 6; b = bid & 63; }
    else           { dir = 1;        b = bid; }

    const float* Whh = dir ? WhhB : WhhF;
    const float* bhh = dir ? bhhB : bhhF;
    const float* xp = g_xp + ((size_t)((ndir == 2) ? dir : 0) * B_ + b) * (size_t)T_ * G3;

    const int j = threadIdx.x;
    const bool is_gate = (j < H_);
    const bool is_z    = (j >= H_ && j < 2 * H_);

    __shared__ __align__(16) float sh_h[H_];
    __shared__ float sh_g[G3];
    __shared__ float sh_xn[H_];

    unsigned long long w[H_ / 2];
    {
        const unsigned long long* wr =
            (const unsigned long long*)(Whh + (size_t)j * H_);
#pragma unroll
        for (int k = 0; k < H_ / 2; k++) w[k] = wr[k];
    }
    const float bj = bhh[j];
    if (is_gate) sh_h[j] = 0.f;
    float h_reg = 0.f;
    __syncthreads();

    const int t0 = dir ? (T_ - 1) : 0;
    const int dt = dir ? -1 : 1;
    const ulonglong2* h4 = (const ulonglong2*)sh_h;

    float xv0 = xp[(size_t)t0 * G3 + j];
    float xv1 = (T_ > 1) ? xp[(size_t)(t0 + dt) * G3 + j] : 0.f;

    // deferred x1 store state (gate threads only)
    float pend_h = 0.f;
    int   pend_t = -1;
    __nv_bfloat16* const x1h_row = g_x1h + (size_t)b * T_ * (2 * H_) + (size_t)dir * H_ + j;
    __nv_bfloat16* const x1l_row = g_x1l + (size_t)b * T_ * (2 * H_) + (size_t)dir * H_ + j;

    for (int s = 0; s < T_; s++) {
        const int t = t0 + s * dt;
        float xv2 = 0.f;
        if (s + 2 < T_) xv2 = xp[(size_t)(t + 2 * dt) * G3 + j];

        // flush previous step's x1 store — overlaps the dot product below
        if (write_x1 && is_gate && pend_t >= 0) {
            __nv_bfloat16 hi = __float2bfloat16(pend_h);
            x1h_row[(size_t)pend_t * (2 * H_)] = hi;
            x1l_row[(size_t)pend_t * (2 * H_)] =
                __float2bfloat16(pend_h - __bfloat162float(hi));
        }

        unsigned long long a0 = 0ull, a1 = 0ull, a2 = 0ull, a3 = 0ull;
#pragma unroll
        for (int k = 0; k < H_ / 8; k++) {
            ulonglong2 hv0 = h4[2 * k];
            ulonglong2 hv1 = h4[2 * k + 1];
            a0 = ffma2(hv0.x, w[4 * k],     a0);
            a1 = ffma2(hv0.y, w[4 * k + 1], a1);
            a2 = ffma2(hv1.x, w[4 * k + 2], a2);
            a3 = ffma2(hv1.y, w[4 * k + 3], a3);
        }
        float2 p0 = u2f(a0), p1 = u2f(a1), p2 = u2f(a2), p3 = u2f(a3);
        float gsum = (p0.x + p0.y) + (p1.x + p1.y) +
                     (p2.x + p2.y) + (p3.x + p3.y) + bj;

        if (is_gate) {
            float r = sigmoid_fast(gsum + xv0);      // own row = r-row
            asm volatile("bar.sync 1, 384;" ::: "memory");
            float z  = sh_g[H_ + j];                 // already sigmoided
            float n  = tanh_fast(sh_xn[j] + r * sh_g[2 * H_ + j]);
            float hn = (1.0f - z) * n + z * h_reg;
            h_reg = hn;
            sh_h[j] = hn;
            pend_h = hn;                             // defer global store
            pend_t = t;
        } else {
            if (is_z) { sh_g[j] = sigmoid_fast(gsum + xv0); }
            else      { sh_g[j] = gsum; sh_xn[j - 2 * H_] = xv0; }
            asm volatile("bar.arrive 1, 384;" ::: "memory");
        }
        __syncthreads();
        xv0 = xv1;
        xv1 = xv2;
    }

    // flush last pending store
    if (write_x1 && is_gate && pend_t >= 0) {
        __nv_bfloat16 hi = __float2bfloat16(pend_h);
        x1h_row[(size_t)pend_t * (2 * H_)] = hi;
        x1l_row[(size_t)pend_t * (2 * H_)] =
            __float2bfloat16(pend_h - __bfloat162float(hi));
    }

    if (write_hN && is_gate) g_hN[b * H_ + j] = h_reg;
}

// =======================================================================
// Decoder
// =======================================================================
__device__ __forceinline__ float mishf(float x) {
    float sp = (x > 20.f) ? x : log1pf(expf(x));
    return x * tanhf(sp);
}
__device__ __forceinline__ float blockReduceSum(float v) {
#pragma unroll
    for (int o = 16; o > 0; o >>= 1) v += __shfl_xor_sync(0xffffffffu, v, o);
    __shared__ float s[4];
    int w = threadIdx.x >> 5;
    if ((threadIdx.x & 31) == 0) s[w] = v;
    __syncthreads();
    v = s[0] + s[1] + s[2] + s[3];
    __syncthreads();
    return v;
}

__global__ __launch_bounds__(128, 1)
void decoder(const float* __restrict__ g1, const float* __restrict__ be1,
             const float* __restrict__ W1, const float* __restrict__ b1,
             const float* __restrict__ g2, const float* __restrict__ be2,
             const float* __restrict__ W2, const float* __restrict__ b2,
             float* __restrict__ out)
{
    const int b = blockIdx.x, j = threadIdx.x;
    __shared__ float sv[H_];

    float v = mishf(g_hN[b * H_ + j]);
    float m = blockReduceSum(v) * (1.0f / H_);
    float d = v - m;
    float var = blockReduceSum(d * d) * (1.0f / H_);
    float y = d * rsqrtf(var + EPS_) * g1[j] + be1[j];
    sv[j] = y;
    __syncthreads();

    float t = b1[j];
#pragma unroll 4
    for (int k = 0; k < H_; k++) t = fmaf(sv[k], W1[j * H_ + k], t);
    float u = mishf(t);
    __syncthreads();

    m = blockReduceSum(u) * (1.0f / H_);
    d = u - m;
    var = blockReduceSum(d * d) * (1.0f / H_);
    float zz = d * rsqrtf(var + EPS_) * g2[j] + be2[j];

    float p = blockReduceSum(zz * W2[j]);
    if (j == 0) out[b] = p + b2[0];
}

// =======================================================================
// Host launcher
// =======================================================================
extern "C" void kernel_launch(void* const* d_in, const int* in_sizes, int n_in,
                              void* d_out, int out_size)
{
    (void)in_sizes; (void)n_in; (void)out_size;
    const float* x     = (const float*)d_in[0];
    const float* Wih0f = (const float*)d_in[1];
    const float* Whh0f = (const float*)d_in[2];
    const float* bih0f = (const float*)d_in[3];
    const float* bhh0f = (const float*)d_in[4];
    const float* Wih0b = (const float*)d_in[5];
    const float* Whh0b = (const float*)d_in[6];
    const float* bih0b = (const float*)d_in[7];
    const float* bhh0b = (const float*)d_in[8];
    // d_in[9..12] = layer-1 forward params: unused by the reference output
    const float* Wih1b = (const float*)d_in[13];
    const float* Whh1b = (const float*)d_in[14];
    const float* bih1b = (const float*)d_in[15];
    const float* bhh1b = (const float*)d_in[16];
    const float* g1  = (const float*)d_in[17];
    const float* be1 = (const float*)d_in[18];
    const float* W1  = (const float*)d_in[19];
    const float* b1  = (const float*)d_in[20];
    const float* g2  = (const float*)d_in[21];
    const float* be2 = (const float*)d_in[22];
    const float* W2  = (const float*)d_in[23];
    const float* b2  = (const float*)d_in[24];

    __nv_bfloat16 *xh, *xl, *w0fh, *w0fl, *w0bh, *w0bl, *w1bh, *w1bl, *x1h, *x1l;
    cudaGetSymbolAddress((void**)&xh,   g_xh);
    cudaGetSymbolAddress((void**)&xl,   g_xl);
    cudaGetSymbolAddress((void**)&w0fh, g_w0fh);
    cudaGetSymbolAddress((void**)&w0fl, g_w0fl);
    cudaGetSymbolAddress((void**)&w0bh, g_w0bh);
    cudaGetSymbolAddress((void**)&w0bl, g_w0bl);
    cudaGetSymbolAddress((void**)&w1bh, g_w1bh);
    cudaGetSymbolAddress((void**)&w1bl, g_w1bl);
    cudaGetSymbolAddress((void**)&x1h,  g_x1h);
    cudaGetSymbolAddress((void**)&x1l,  g_x1l);

    static int smem_set = 0;
    if (!smem_set) {
        cudaFuncSetAttribute(hmma_gemm,
                             cudaFuncAttributeMaxDynamicSharedMemorySize, HG_SMEM);
        smem_set = 1;
    }

    // split inputs into bf16 hi/lo
    split_bf16<<<4096, 256>>>(x, xh, xl, (size_t)MTOT * IN_);
    split_bf16<<<64, 256>>>(Wih0f, w0fh, w0fl, (size_t)G3 * IN_);
    split_bf16<<<64, 256>>>(Wih0b, w0bh, w0bl, (size_t)G3 * IN_);
    split_bf16<<<32, 256>>>(Wih1b, w1bh, w1bl, (size_t)G3 * 2 * H_);

    // layer-0 projections: grid (n-tile, m-tile, dir) — n fastest for A L2 reuse
    {
        dim3 grid(3, MTOT / 128, 2);
        hmma_gemm<<<grid, 256, HG_SMEM>>>(xh, xl, IN_,
                                          w0fh, w0fl, bih0f,
                                          w0bh, w0bl, bih0b);
    }
    gru_scan<<<128, 384>>>(Whh0f, bhh0f, Whh0b, bhh0b, 1, 0, 2);
    // layer-1 backward projection
    {
        dim3 grid(3, MTOT / 128, 1);
        hmma_gemm<<<grid, 256, HG_SMEM>>>(x1h, x1l, 2 * H_,
                                          w1bh, w1bl, bih1b,
                                          w1bh, w1bl, bih1b);
    }
    gru_scan<<<64, 384>>>(Whh1b, bhh1b, Whh1b, bhh1b, 0, 1, 1);
    decoder<<<64, 128>>>(g1, be1, W1, b1, g2, be2, W2, b2, (float*)d_out);
}

// round 15
// speedup vs baseline: 2.1675x; 1.0638x over previous
#include <cuda_runtime.h>
#include <cuda_bf16.h>
#include <cuda_fp16.h>
#include <math.h>
#include <stdint.h>

// Problem dims
#define B_   64
#define T_   2048
#define IN_  512
#define H_   128
#define G3   384            // 3*H
#define EPS_ 1e-5f
#define MTOT (B_ * T_)      // 131072

// ---------------- device scratch ----------------
__device__ float g_xp[(size_t)2 * B_ * T_ * G3];              // [dir][B][T][3H] fp32
__device__ __half g_xf[(size_t)MTOT * IN_];                   // x as fp16 (2-combo A)
__device__ __half g_w0fh16[G3 * IN_], g_w0fl16[G3 * IN_];     // W0f fp16 hi/lo
__device__ __half g_w0bh16[G3 * IN_], g_w0bl16[G3 * IN_];     // W0b fp16 hi/lo
__device__ __nv_bfloat16 g_x1h[(size_t)MTOT * 2 * H_];
__device__ __nv_bfloat16 g_x1l[(size_t)MTOT * 2 * H_];
__device__ __nv_bfloat16 g_w1bh[G3 * 2 * H_], g_w1bl[G3 * 2 * H_];
__device__ float g_hN[B_ * H_];

// ---------------- helpers ----------------
__device__ __forceinline__ unsigned long long ffma2(unsigned long long a,
                                                    unsigned long long b,
                                                    unsigned long long c) {
    unsigned long long d;
    asm("fma.rn.f32x2 %0, %1, %2, %3;" : "=l"(d) : "l"(a), "l"(b), "l"(c));
    return d;
}
__device__ __forceinline__ float2 u2f(unsigned long long u) {
    float2 f;
    asm("mov.b64 {%0, %1}, %2;" : "=f"(f.x), "=f"(f.y) : "l"(u));
    return f;
}
__device__ __forceinline__ float tanh_fast(float x) {
    float y;
    asm("tanh.approx.f32 %0, %1;" : "=f"(y) : "f"(x));
    return y;
}
__device__ __forceinline__ float sigmoid_fast(float x) {
    return fmaf(0.5f, tanh_fast(0.5f * x), 0.5f);
}
__device__ __forceinline__ void cp16(uint32_t dst, const void* src) {
    asm volatile("cp.async.cg.shared.global [%0], [%1], 16;" :: "r"(dst), "l"(src));
}
__device__ __forceinline__ uint32_t s2u(const void* p) {
    uint32_t a;
    asm("{ .reg .u64 t; cvta.to.shared.u64 t, %1; cvt.u32.u64 %0, t; }"
        : "=r"(a) : "l"(p));
    return a;
}
__device__ __forceinline__ void ldsm4(uint32_t& r0, uint32_t& r1,
                                      uint32_t& r2, uint32_t& r3, uint32_t a) {
    asm volatile("ldmatrix.sync.aligned.m8n8.x4.shared.b16 {%0,%1,%2,%3}, [%4];"
                 : "=r"(r0), "=r"(r1), "=r"(r2), "=r"(r3) : "r"(a));
}
__device__ __forceinline__ void mma16816(float* c, uint32_t a0, uint32_t a1,
                                         uint32_t a2, uint32_t a3,
                                         uint32_t b0, uint32_t b1) {
    asm volatile(
        "mma.sync.aligned.m16n8k16.row.col.f32.bf16.bf16.f32 "
        "{%0,%1,%2,%3}, {%4,%5,%6,%7}, {%8,%9}, {%0,%1,%2,%3};"
        : "+f"(c[0]), "+f"(c[1]), "+f"(c[2]), "+f"(c[3])
        : "r"(a0), "r"(a1), "r"(a2), "r"(a3), "r"(b0), "r"(b1));
}
__device__ __forceinline__ void mma16816h(float* c, uint32_t a0, uint32_t a1,
                                          uint32_t a2, uint32_t a3,
                                          uint32_t b0, uint32_t b1) {
    asm volatile(
        "mma.sync.aligned.m16n8k16.row.col.f32.f16.f16.f32 "
        "{%0,%1,%2,%3}, {%4,%5,%6,%7}, {%8,%9}, {%0,%1,%2,%3};"
        : "+f"(c[0]), "+f"(c[1]), "+f"(c[2]), "+f"(c[3])
        : "r"(a0), "r"(a1), "r"(a2), "r"(a3), "r"(b0), "r"(b1));
}

// =======================================================================
// Conversion kernels
// =======================================================================
__global__ void split_bf16(const float* __restrict__ src,
                           __nv_bfloat16* __restrict__ dh,
                           __nv_bfloat16* __restrict__ dl, size_t n)
{
    size_t i = ((size_t)blockIdx.x * blockDim.x + threadIdx.x) * 4;
    size_t stride = (size_t)gridDim.x * blockDim.x * 4;
    for (; i < n; i += stride) {
        float4 v = *(const float4*)(src + i);
        __nv_bfloat16 h0 = __float2bfloat16(v.x);
        __nv_bfloat16 h1 = __float2bfloat16(v.y);
        __nv_bfloat16 h2 = __float2bfloat16(v.z);
        __nv_bfloat16 h3 = __float2bfloat16(v.w);
        __nv_bfloat16 l0 = __float2bfloat16(v.x - __bfloat162float(h0));
        __nv_bfloat16 l1 = __float2bfloat16(v.y - __bfloat162float(h1));
        __nv_bfloat16 l2 = __float2bfloat16(v.z - __bfloat162float(h2));
        __nv_bfloat16 l3 = __float2bfloat16(v.w - __bfloat162float(h3));
        *(__nv_bfloat162*)(dh + i)     = __nv_bfloat162(h0, h1);
        *(__nv_bfloat162*)(dh + i + 2) = __nv_bfloat162(h2, h3);
        *(__nv_bfloat162*)(dl + i)     = __nv_bfloat162(l0, l1);
        *(__nv_bfloat162*)(dl + i + 2) = __nv_bfloat162(l2, l3);
    }
}

__global__ void split_f16(const float* __restrict__ src,
                          __half* __restrict__ dh,
                          __half* __restrict__ dl, size_t n)
{
    size_t i = ((size_t)blockIdx.x * blockDim.x + threadIdx.x) * 4;
    size_t stride = (size_t)gridDim.x * blockDim.x * 4;
    for (; i < n; i += stride) {
        float4 v = *(const float4*)(src + i);
        __half h0 = __float2half(v.x), h1 = __float2half(v.y);
        __half h2 = __float2half(v.z), h3 = __float2half(v.w);
        __half l0 = __float2half(v.x - __half2float(h0));
        __half l1 = __float2half(v.y - __half2float(h1));
        __half l2 = __float2half(v.z - __half2float(h2));
        __half l3 = __float2half(v.w - __half2float(h3));
        *(__half2*)(dh + i)     = __half2(h0, h1);
        *(__half2*)(dh + i + 2) = __half2(h2, h3);
        *(__half2*)(dl + i)     = __half2(l0, l1);
        *(__half2*)(dl + i + 2) = __half2(l2, l3);
    }
}

__global__ void conv_f16(const float* __restrict__ src,
                         __half* __restrict__ d, size_t n)
{
    size_t i = ((size_t)blockIdx.x * blockDim.x + threadIdx.x) * 4;
    size_t stride = (size_t)gridDim.x * blockDim.x * 4;
    for (; i < n; i += stride) {
        float4 v = *(const float4*)(src + i);
        *(__half2*)(d + i)     = __half2(__float2half(v.x), __float2half(v.y));
        *(__half2*)(d + i + 2) = __half2(__float2half(v.z), __float2half(v.w));
    }
}

// =======================================================================
// Layer-0 GEMM: fp16 2-combo.  C = Ah*Wh + Ah*Wl + bias  (= Ah*W)
// CTA 128x128, 8 warps (2m x 4n), warp tile m64n32, K-chunk 32.
// Identical structure to the verified bf16 GEMM; one A array, 4 stages.
// =======================================================================
#define SA 40                 // padded row stride in 16-bit units (80 B)
#define TILEB (128 * SA)      // elements per tile array
#define T2B (TILEB * 2)       // bytes per tile array (10240)
#define BUF3 (3 * T2B)        // X, Yh, Yl  (30720 B)
#define HG16_SMEM (2 * BUF3 + 512)

__global__ __launch_bounds__(256, 2)
void hmma_gemm16(const __half* __restrict__ Xf, int K,
                 const __half* __restrict__ Wh0, const __half* __restrict__ Wl0,
                 const float* __restrict__ b0,
                 const __half* __restrict__ Wh1, const __half* __restrict__ Wl1,
                 const float* __restrict__ b1)
{
    extern __shared__ __half smh[];
    const __half* Wh = blockIdx.z ? Wh1 : Wh0;
    const __half* Wl = blockIdx.z ? Wl1 : Wl0;
    const float* bias = blockIdx.z ? b1 : b0;
    float* C = g_xp + (size_t)blockIdx.z * MTOT * G3;

    float* sbias = (float*)((char*)smh + 2 * BUF3);
    const uint32_t smu = s2u(smh);

    const int tid  = threadIdx.x;
    const int wid  = tid >> 5;
    const int lane = tid & 31;
    const int wm   = wid >> 2;
    const int wn   = wid & 3;
    const int gg   = lane >> 2;
    const int t    = lane & 3;
    const int rrow = lane & 7;
    const int grp  = lane >> 3;

    const size_t rowA0 = (size_t)blockIdx.y * 128;
    const int    ncol0 = blockIdx.x * 128;

    if (tid < 128) sbias[tid] = bias[ncol0 + tid];

    int lrow[2], lq[2];
#pragma unroll
    for (int p = 0; p < 2; p++) {
        int u = p * 256 + tid;
        lrow[p] = u >> 2;
        lq[p]   = u & 3;
    }

    float c[4][4][4];
#pragma unroll
    for (int i = 0; i < 4; i++)
#pragma unroll
        for (int j = 0; j < 4; j++)
#pragma unroll
            for (int q = 0; q < 4; q++) c[i][j][q] = 0.f;

    const int nkt = K / 32;

    auto load_tile = [&](int kt, int b) {
        uint32_t base = smu + (uint32_t)b * BUF3;
#pragma unroll
        for (int p = 0; p < 2; p++) {
            int row = lrow[p], q = lq[p];
            uint32_t doff = (uint32_t)(row * SA + q * 8) * 2;
            size_t ga = (rowA0 + row) * (size_t)K + (size_t)kt * 32 + q * 8;
            size_t gw = ((size_t)ncol0 + row) * (size_t)K + (size_t)kt * 32 + q * 8;
            cp16(base + doff,           Xf + ga);
            cp16(base + T2B + doff,     Wh + gw);
            cp16(base + 2 * T2B + doff, Wl + gw);
        }
    };

    load_tile(0, 0);
    asm volatile("cp.async.commit_group;");

    const uint32_t a_lane = (uint32_t)((wm * 64 + rrow + (grp & 1) * 8) * SA + (grp >> 1) * 8);
    const uint32_t b_lane = (uint32_t)((wn * 32 + (grp >> 1) * 8 + rrow) * SA + (grp & 1) * 8);

    for (int kt = 0; kt < nkt; kt++) {
        if (kt + 1 < nkt) {
            load_tile(kt + 1, (kt + 1) & 1);
            asm volatile("cp.async.commit_group;");
            asm volatile("cp.async.wait_group 1;");
        } else {
            asm volatile("cp.async.wait_group 0;");
        }
        __syncthreads();

        const uint32_t buf = smu + (uint32_t)(kt & 1) * BUF3;

        // stage s = (combo, ks): combo in {X*Wh, X*Wl}
#pragma unroll
        for (int s = 0; s < 4; s++) {
            const int combo = s >> 1, ks = s & 1;
            const uint32_t Ab = buf;                                 // X
            const uint32_t Wb = buf + (combo ? 2 * T2B : T2B);       // Wh / Wl
            const uint32_t kof2 = (uint32_t)(ks * 16) * 2;

            uint32_t fb[4][2];
#pragma unroll
            for (int jj = 0; jj < 2; jj++) {
                uint32_t ad = Wb + (b_lane + (uint32_t)(jj * 16 * SA)) * 2 + kof2;
                ldsm4(fb[2 * jj][0], fb[2 * jj][1],
                      fb[2 * jj + 1][0], fb[2 * jj + 1][1], ad);
            }
            uint32_t fa[4][4];
#pragma unroll
            for (int i = 0; i < 4; i++) {
                uint32_t ad = Ab + (a_lane + (uint32_t)(i * 16 * SA)) * 2 + kof2;
                ldsm4(fa[i][0], fa[i][1], fa[i][2], fa[i][3], ad);
            }
#pragma unroll
            for (int i = 0; i < 4; i++)
#pragma unroll
                for (int j = 0; j < 4; j++)
                    mma16816h(c[i][j], fa[i][0], fa[i][1], fa[i][2], fa[i][3],
                              fb[j][0], fb[j][1]);
        }
        __syncthreads();
    }

    // epilogue
#pragma unroll
    for (int i = 0; i < 4; i++) {
        size_t r0 = rowA0 + wm * 64 + i * 16 + gg;
        size_t r1 = r0 + 8;
#pragma unroll
        for (int j = 0; j < 4; j++) {
            int cl = wn * 32 + j * 8 + 2 * t;
            float b0v = sbias[cl], b1v = sbias[cl + 1];
            *(float2*)(C + r0 * G3 + ncol0 + cl) =
                make_float2(c[i][j][0] + b0v, c[i][j][1] + b1v);
            *(float2*)(C + r1 * G3 + ncol0 + cl) =
                make_float2(c[i][j][2] + b0v, c[i][j][3] + b1v);
        }
    }
}

// =======================================================================
// Layer-1 GEMM: verified bf16 3-combo (unchanged from R14).
// =======================================================================
#define TILE4 (128 * SA)
#define BUFB  (4 * TILE4)     // Ah,Al,Wh,Wl
#define HG_SMEM (2 * BUFB * 2 + 512)

__global__ __launch_bounds__(256, 2)
void hmma_gemm(const __nv_bfloat16* __restrict__ Ah,
               const __nv_bfloat16* __restrict__ Al, int K,
               const __nv_bfloat16* __restrict__ Wh0,
               const __nv_bfloat16* __restrict__ Wl0, const float* __restrict__ b0,
               const __nv_bfloat16* __restrict__ Wh1,
               const __nv_bfloat16* __restrict__ Wl1, const float* __restrict__ b1)
{
    extern __shared__ __nv_bfloat16 sm[];
    const __nv_bfloat16* Wh = blockIdx.z ? Wh1 : Wh0;
    const __nv_bfloat16* Wl = blockIdx.z ? Wl1 : Wl0;
    const float* bias = blockIdx.z ? b1 : b0;
    float* C = g_xp + (size_t)blockIdx.z * MTOT * G3;

    float* sbias = (float*)(sm + 2 * BUFB);
    const uint32_t smu = s2u(sm);

    const int tid  = threadIdx.x;
    const int wid  = tid >> 5;
    const int lane = tid & 31;
    const int wm   = wid >> 2;
    const int wn   = wid & 3;
    const int gg   = lane >> 2;
    const int t    = lane & 3;
    const int rrow = lane & 7;
    const int grp  = lane >> 3;

    const size_t rowA0 = (size_t)blockIdx.y * 128;
    const int    ncol0 = blockIdx.x * 128;

    if (tid < 128) sbias[tid] = bias[ncol0 + tid];

    int lrow[2], lq[2];
#pragma unroll
    for (int p = 0; p < 2; p++) {
        int u = p * 256 + tid;
        lrow[p] = u >> 2;
        lq[p]   = u & 3;
    }

    float c[4][4][4];
#pragma unroll
    for (int i = 0; i < 4; i++)
#pragma unroll
        for (int j = 0; j < 4; j++)
#pragma unroll
            for (int q = 0; q < 4; q++) c[i][j][q] = 0.f;

    const int nkt = K / 32;

    auto load_tile = [&](int kt, int b) {
        uint32_t base = smu + (uint32_t)b * BUFB * 2;
#pragma unroll
        for (int p = 0; p < 2; p++) {
            int row = lrow[p], q = lq[p];
            uint32_t doff = (uint32_t)(row * SA + q * 8) * 2;
            size_t ga = (rowA0 + row) * (size_t)K + (size_t)kt * 32 + q * 8;
            size_t gw = ((size_t)ncol0 + row) * (size_t)K + (size_t)kt * 32 + q * 8;
            cp16(base + 0 * TILE4 * 2 + doff, Ah + ga);
            cp16(base + 1 * TILE4 * 2 + doff, Al + ga);
            cp16(base + 2 * TILE4 * 2 + doff, Wh + gw);
            cp16(base + 3 * TILE4 * 2 + doff, Wl + gw);
        }
    };

    load_tile(0, 0);
    asm volatile("cp.async.commit_group;");

    const uint32_t a_lane = (uint32_t)((wm * 64 + rrow + (grp & 1) * 8) * SA + (grp >> 1) * 8);
    const uint32_t b_lane = (uint32_t)((wn * 32 + (grp >> 1) * 8 + rrow) * SA + (grp & 1) * 8);

    for (int kt = 0; kt < nkt; kt++) {
        if (kt + 1 < nkt) {
            load_tile(kt + 1, (kt + 1) & 1);
            asm volatile("cp.async.commit_group;");
            asm volatile("cp.async.wait_group 1;");
        } else {
            asm volatile("cp.async.wait_group 0;");
        }
        __syncthreads();

        const uint32_t buf = smu + (uint32_t)(kt & 1) * BUFB * 2;

#pragma unroll
        for (int s = 0; s < 6; s++) {
            const int combo = s >> 1, ks = s & 1;
            const uint32_t Ab = buf + (combo == 2 ? 1 : 0) * TILE4 * 2;
            const uint32_t Wb = buf + (combo == 1 ? 3 : 2) * TILE4 * 2;
            const uint32_t kof2 = (uint32_t)(ks * 16) * 2;

            uint32_t fb[4][2];
#pragma unroll
            for (int jj = 0; jj < 2; jj++) {
                uint32_t ad = Wb + (b_lane + (uint32_t)(jj * 16 * SA)) * 2 + kof2;
                ldsm4(fb[2 * jj][0], fb[2 * jj][1],
                      fb[2 * jj + 1][0], fb[2 * jj + 1][1], ad);
            }
            uint32_t fa[4][4];
#pragma unroll
            for (int i = 0; i < 4; i++) {
                uint32_t ad = Ab + (a_lane + (uint32_t)(i * 16 * SA)) * 2 + kof2;
                ldsm4(fa[i][0], fa[i][1], fa[i][2], fa[i][3], ad);
            }
#pragma unroll
            for (int i = 0; i < 4; i++)
#pragma unroll
                for (int j = 0; j < 4; j++)
                    mma16816(c[i][j], fa[i][0], fa[i][1], fa[i][2], fa[i][3],
                             fb[j][0], fb[j][1]);
        }
        __syncthreads();
    }

#pragma unroll
    for (int i = 0; i < 4; i++) {
        size_t r0 = rowA0 + wm * 64 + i * 16 + gg;
        size_t r1 = r0 + 8;
#pragma unroll
        for (int j = 0; j < 4; j++) {
            int cl = wn * 32 + j * 8 + 2 * t;
            float b0v = sbias[cl], b1v = sbias[cl + 1];
            *(float2*)(C + r0 * G3 + ncol0 + cl) =
                make_float2(c[i][j][0] + b0v, c[i][j][1] + b1v);
            *(float2*)(C + r1 * G3 + ncol0 + cl) =
                make_float2(c[i][j][2] + b0v, c[i][j][3] + b1v);
        }
    }
}

// =======================================================================
// GRU sequential scan (verified R14 version, unchanged).
// =======================================================================
__global__ __launch_bounds__(384, 1)
void gru_scan(const float* __restrict__ WhhF, const float* __restrict__ bhhF,
              const float* __restrict__ WhhB, const float* __restrict__ bhhB,
              int write_x1, int write_hN, int ndir)
{
    int bid = blockIdx.x;
    int dir, b;
    if (ndir == 2) { dir = bid >> 6; b = bid & 63; }
    else           { dir = 1;        b = bid; }

    const float* Whh = dir ? WhhB : WhhF;
    const float* bhh = dir ? bhhB : bhhF;
    const float* xp = g_xp + ((size_t)((ndir == 2) ? dir : 0) * B_ + b) * (size_t)T_ * G3;

    const int j = threadIdx.x;
    const bool is_gate = (j < H_);
    const bool is_z    = (j >= H_ && j < 2 * H_);

    __shared__ __align__(16) float sh_h[H_];
    __shared__ float sh_g[G3];
    __shared__ float sh_xn[H_];

    unsigned long long w[H_ / 2];
    {
        const unsigned long long* wr =
            (const unsigned long long*)(Whh + (size_t)j * H_);
#pragma unroll
        for (int k = 0; k < H_ / 2; k++) w[k] = wr[k];
    }
    const float bj = bhh[j];
    if (is_gate) sh_h[j] = 0.f;
    float h_reg = 0.f;
    __syncthreads();

    const int t0 = dir ? (T_ - 1) : 0;
    const int dt = dir ? -1 : 1;
    const ulonglong2* h4 = (const ulonglong2*)sh_h;

    float xv0 = xp[(size_t)t0 * G3 + j];
    float xv1 = (T_ > 1) ? xp[(size_t)(t0 + dt) * G3 + j] : 0.f;

    float pend_h = 0.f;
    int   pend_t = -1;
    __nv_bfloat16* const x1h_row = g_x1h + (size_t)b * T_ * (2 * H_) + (size_t)dir * H_ + j;
    __nv_bfloat16* const x1l_row = g_x1l + (size_t)b * T_ * (2 * H_) + (size_t)dir * H_ + j;

    for (int s = 0; s < T_; s++) {
        const int t = t0 + s * dt;
        float xv2 = 0.f;
        if (s + 2 < T_) xv2 = xp[(size_t)(t + 2 * dt) * G3 + j];

        if (write_x1 && is_gate && pend_t >= 0) {
            __nv_bfloat16 hi = __float2bfloat16(pend_h);
            x1h_row[(size_t)pend_t * (2 * H_)] = hi;
            x1l_row[(size_t)pend_t * (2 * H_)] =
                __float2bfloat16(pend_h - __bfloat162float(hi));
        }

        unsigned long long a0 = 0ull, a1 = 0ull, a2 = 0ull, a3 = 0ull;
#pragma unroll
        for (int k = 0; k < H_ / 8; k++) {
            ulonglong2 hv0 = h4[2 * k];
            ulonglong2 hv1 = h4[2 * k + 1];
            a0 = ffma2(hv0.x, w[4 * k],     a0);
            a1 = ffma2(hv0.y, w[4 * k + 1], a1);
            a2 = ffma2(hv1.x, w[4 * k + 2], a2);
            a3 = ffma2(hv1.y, w[4 * k + 3], a3);
        }
        float2 p0 = u2f(a0), p1 = u2f(a1), p2 = u2f(a2), p3 = u2f(a3);
        float gsum = (p0.x + p0.y) + (p1.x + p1.y) +
                     (p2.x + p2.y) + (p3.x + p3.y) + bj;

        if (is_gate) {
            float r = sigmoid_fast(gsum + xv0);
            asm volatile("bar.sync 1, 384;" ::: "memory");
            float z  = sh_g[H_ + j];
            float n  = tanh_fast(sh_xn[j] + r * sh_g[2 * H_ + j]);
            float hn = (1.0f - z) * n + z * h_reg;
            h_reg = hn;
            sh_h[j] = hn;
            pend_h = hn;
            pend_t = t;
        } else {
            if (is_z) { sh_g[j] = sigmoid_fast(gsum + xv0); }
            else      { sh_g[j] = gsum; sh_xn[j - 2 * H_] = xv0; }
            asm volatile("bar.arrive 1, 384;" ::: "memory");
        }
        __syncthreads();
        xv0 = xv1;
        xv1 = xv2;
    }

    if (write_x1 && is_gate && pend_t >= 0) {
        __nv_bfloat16 hi = __float2bfloat16(pend_h);
        x1h_row[(size_t)pend_t * (2 * H_)] = hi;
        x1l_row[(size_t)pend_t * (2 * H_)] =
            __float2bfloat16(pend_h - __bfloat162float(hi));
    }

    if (write_hN && is_gate) g_hN[b * H_ + j] = h_reg;
}

// =======================================================================
// Decoder (unchanged)
// =======================================================================
__device__ __forceinline__ float mishf(float x) {
    float sp = (x > 20.f) ? x : log1pf(expf(x));
    return x * tanhf(sp);
}
__device__ __forceinline__ float blockReduceSum(float v) {
#pragma unroll
    for (int o = 16; o > 0; o >>= 1) v += __shfl_xor_sync(0xffffffffu, v, o);
    __shared__ float s[4];
    int w = threadIdx.x >> 5;
    if ((threadIdx.x & 31) == 0) s[w] = v;
    __syncthreads();
    v = s[0] + s[1] + s[2] + s[3];
    __syncthreads();
    return v;
}

__global__ __launch_bounds__(128, 1)
void decoder(const float* __restrict__ g1, const float* __restrict__ be1,
             const float* __restrict__ W1, const float* __restrict__ b1,
             const float* __restrict__ g2, const float* __restrict__ be2,
             const float* __restrict__ W2, const float* __restrict__ b2,
             float* __restrict__ out)
{
    const int b = blockIdx.x, j = threadIdx.x;
    __shared__ float sv[H_];

    float v = mishf(g_hN[b * H_ + j]);
    float m = blockReduceSum(v) * (1.0f / H_);
    float d = v - m;
    float var = blockReduceSum(d * d) * (1.0f / H_);
    float y = d * rsqrtf(var + EPS_) * g1[j] + be1[j];
    sv[j] = y;
    __syncthreads();

    float t = b1[j];
#pragma unroll 4
    for (int k = 0; k < H_; k++) t = fmaf(sv[k], W1[j * H_ + k], t);
    float u = mishf(t);
    __syncthreads();

    m = blockReduceSum(u) * (1.0f / H_);
    d = u - m;
    var = blockReduceSum(d * d) * (1.0f / H_);
    float zz = d * rsqrtf(var + EPS_) * g2[j] + be2[j];

    float p = blockReduceSum(zz * W2[j]);
    if (j == 0) out[b] = p + b2[0];
}

// =======================================================================
// Host launcher
// =======================================================================
extern "C" void kernel_launch(void* const* d_in, const int* in_sizes, int n_in,
                              void* d_out, int out_size)
{
    (void)in_sizes; (void)n_in; (void)out_size;
    const float* x     = (const float*)d_in[0];
    const float* Wih0f = (const float*)d_in[1];
    const float* Whh0f = (const float*)d_in[2];
    const float* bih0f = (const float*)d_in[3];
    const float* bhh0f = (const float*)d_in[4];
    const float* Wih0b = (const float*)d_in[5];
    const float* Whh0b = (const float*)d_in[6];
    const float* bih0b = (const float*)d_in[7];
    const float* bhh0b = (const float*)d_in[8];
    // d_in[9..12] = layer-1 forward params: unused by the reference output
    const float* Wih1b = (const float*)d_in[13];
    const float* Whh1b = (const float*)d_in[14];
    const float* bih1b = (const float*)d_in[15];
    const float* bhh1b = (const float*)d_in[16];
    const float* g1  = (const float*)d_in[17];
    const float* be1 = (const float*)d_in[18];
    const float* W1  = (const float*)d_in[19];
    const float* b1  = (const float*)d_in[20];
    const float* g2  = (const float*)d_in[21];
    const float* be2 = (const float*)d_in[22];
    const float* W2  = (const float*)d_in[23];
    const float* b2  = (const float*)d_in[24];

    __half *xf, *w0fh, *w0fl, *w0bh, *w0bl;
    __nv_bfloat16 *w1bh, *w1bl, *x1h, *x1l;
    cudaGetSymbolAddress((void**)&xf,   g_xf);
    cudaGetSymbolAddress((void**)&w0fh, g_w0fh16);
    cudaGetSymbolAddress((void**)&w0fl, g_w0fl16);
    cudaGetSymbolAddress((void**)&w0bh, g_w0bh16);
    cudaGetSymbolAddress((void**)&w0bl, g_w0bl16);
    cudaGetSymbolAddress((void**)&w1bh, g_w1bh);
    cudaGetSymbolAddress((void**)&w1bl, g_w1bl);
    cudaGetSymbolAddress((void**)&x1h,  g_x1h);
    cudaGetSymbolAddress((void**)&x1l,  g_x1l);

    static int smem_set = 0;
    if (!smem_set) {
        cudaFuncSetAttribute(hmma_gemm,
                             cudaFuncAttributeMaxDynamicSharedMemorySize, HG_SMEM);
        cudaFuncSetAttribute(hmma_gemm16,
                             cudaFuncAttributeMaxDynamicSharedMemorySize, HG16_SMEM);
        smem_set = 1;
    }

    // conversions
    conv_f16<<<4096, 256>>>(x, xf, (size_t)MTOT * IN_);
    split_f16<<<64, 256>>>(Wih0f, w0fh, w0fl, (size_t)G3 * IN_);
    split_f16<<<64, 256>>>(Wih0b, w0bh, w0bl, (size_t)G3 * IN_);
    split_bf16<<<32, 256>>>(Wih1b, w1bh, w1bl, (size_t)G3 * 2 * H_);

    // layer-0 projections: fp16 2-combo, grid (n-tile, m-tile, dir)
    {
        dim3 grid(3, MTOT / 128, 2);
        hmma_gemm16<<<grid, 256, HG16_SMEM>>>(xf, IN_,
                                              w0fh, w0fl, bih0f,
                                              w0bh, w0bl, bih0b);
    }
    gru_scan<<<128, 384>>>(Whh0f, bhh0f, Whh0b, bhh0b, 1, 0, 2);
    // layer-1 backward projection (verified bf16 3-combo)
    {
        dim3 grid(3, MTOT / 128, 1);
        hmma_gemm<<<grid, 256, HG_SMEM>>>(x1h, x1l, 2 * H_,
                                          w1bh, w1bl, bih1b,
                                          w1bh, w1bl, bih1b);
    }
    gru_scan<<<64, 384>>>(Whh1b, bhh1b, Whh1b, bhh1b, 0, 1, 1);
    decoder<<<64, 128>>>(g1, be1, W1, b1, g2, be2, W2, b2, (float*)d_out);
}

// round 17
// speedup vs baseline: 2.3736x; 1.0951x over previous
#include <cuda_runtime.h>
#include <cuda_fp16.h>
#include <math.h>
#include <stdint.h>

// Problem dims
#define B_   64
#define T_   2048
#define IN_  512
#define H_   128
#define G3   384            // 3*H
#define EPS_ 1e-5f
#define MTOT (B_ * T_)      // 131072

// ---------------- device scratch ----------------
__device__ float g_xp[(size_t)2 * B_ * T_ * G3];              // [dir][B][T][3H] fp32
__device__ __half g_xf[(size_t)MTOT * IN_];                   // x as fp16
__device__ __half g_w0f16[G3 * IN_], g_w0b16[G3 * IN_];       // W0 single fp16
__device__ __half g_x1f[(size_t)MTOT * 2 * H_];               // x1 as fp16
__device__ __half g_w1bh16[G3 * 2 * H_], g_w1bl16[G3 * 2 * H_]; // W1b fp16 hi/lo
__device__ float g_hN[B_ * H_];

// ---------------- helpers ----------------
__device__ __forceinline__ unsigned long long ffma2(unsigned long long a,
                                                    unsigned long long b,
                                                    unsigned long long c) {
    unsigned long long d;
    asm("fma.rn.f32x2 %0, %1, %2, %3;" : "=l"(d) : "l"(a), "l"(b), "l"(c));
    return d;
}
__device__ __forceinline__ float2 u2f(unsigned long long u) {
    float2 f;
    asm("mov.b64 {%0, %1}, %2;" : "=f"(f.x), "=f"(f.y) : "l"(u));
    return f;
}
__device__ __forceinline__ float tanh_fast(float x) {
    float y;
    asm("tanh.approx.f32 %0, %1;" : "=f"(y) : "f"(x));
    return y;
}
__device__ __forceinline__ float sigmoid_fast(float x) {
    return fmaf(0.5f, tanh_fast(0.5f * x), 0.5f);
}
__device__ __forceinline__ void cp16(uint32_t dst, const void* src) {
    asm volatile("cp.async.cg.shared.global [%0], [%1], 16;" :: "r"(dst), "l"(src));
}
__device__ __forceinline__ uint32_t s2u(const void* p) {
    uint32_t a;
    asm("{ .reg .u64 t; cvta.to.shared.u64 t, %1; cvt.u32.u64 %0, t; }"
        : "=r"(a) : "l"(p));
    return a;
}
__device__ __forceinline__ void ldsm4(uint32_t& r0, uint32_t& r1,
                                      uint32_t& r2, uint32_t& r3, uint32_t a) {
    asm volatile("ldmatrix.sync.aligned.m8n8.x4.shared.b16 {%0,%1,%2,%3}, [%4];"
                 : "=r"(r0), "=r"(r1), "=r"(r2), "=r"(r3) : "r"(a));
}
__device__ __forceinline__ void mma16816h(float* c, uint32_t a0, uint32_t a1,
                                          uint32_t a2, uint32_t a3,
                                          uint32_t b0, uint32_t b1) {
    asm volatile(
        "mma.sync.aligned.m16n8k16.row.col.f32.f16.f16.f32 "
        "{%0,%1,%2,%3}, {%4,%5,%6,%7}, {%8,%9}, {%0,%1,%2,%3};"
        : "+f"(c[0]), "+f"(c[1]), "+f"(c[2]), "+f"(c[3])
        : "r"(a0), "r"(a1), "r"(a2), "r"(a3), "r"(b0), "r"(b1));
}

// =======================================================================
// Conversion kernels
// =======================================================================
__global__ void conv_f16(const float* __restrict__ src,
                         __half* __restrict__ d, size_t n)
{
    size_t i = ((size_t)blockIdx.x * blockDim.x + threadIdx.x) * 4;
    size_t stride = (size_t)gridDim.x * blockDim.x * 4;
    for (; i < n; i += stride) {
        float4 v = *(const float4*)(src + i);
        *(__half2*)(d + i)     = __half2(__float2half(v.x), __float2half(v.y));
        *(__half2*)(d + i + 2) = __half2(__float2half(v.z), __float2half(v.w));
    }
}

__global__ void split_f16(const float* __restrict__ src,
                          __half* __restrict__ dh,
                          __half* __restrict__ dl, size_t n)
{
    size_t i = ((size_t)blockIdx.x * blockDim.x + threadIdx.x) * 4;
    size_t stride = (size_t)gridDim.x * blockDim.x * 4;
    for (; i < n; i += stride) {
        float4 v = *(const float4*)(src + i);
        __half h0 = __float2half(v.x), h1 = __float2half(v.y);
        __half h2 = __float2half(v.z), h3 = __float2half(v.w);
        __half l0 = __float2half(v.x - __half2float(h0));
        __half l1 = __float2half(v.y - __half2float(h1));
        __half l2 = __float2half(v.z - __half2float(h2));
        __half l3 = __float2half(v.w - __half2float(h3));
        *(__half2*)(dh + i)     = __half2(h0, h1);
        *(__half2*)(dh + i + 2) = __half2(h2, h3);
        *(__half2*)(dl + i)     = __half2(l0, l1);
        *(__half2*)(dl + i + 2) = __half2(l2, l3);
    }
}

// =======================================================================
// Shared GEMM geometry
// =======================================================================
#define SA 40                 // padded row stride in 16-bit units (80 B)
#define TILEB (128 * SA)      // elements per tile array
#define T2B (TILEB * 2)       // bytes per tile array (10240)

// =======================================================================
// Layer-0 GEMM: fp16 1-combo.  C = X*W + bias.
// CTA 128x128, 8 warps (2m x 4n), warp tile m64n32, K-chunk 32, 2 stages.
// =======================================================================
#define BUF2 (2 * T2B)        // X, W (20480 B)
#define HG1_SMEM (2 * BUF2 + 512)

__global__ __launch_bounds__(256, 2)
void hmma_gemm_1c(const __half* __restrict__ Xf, int K,
                  const __half* __restrict__ W0, const float* __restrict__ b0,
                  const __half* __restrict__ W1, const float* __restrict__ b1)
{
    extern __shared__ __half smh[];
    const __half* W = blockIdx.z ? W1 : W0;
    const float* bias = blockIdx.z ? b1 : b0;
    float* C = g_xp + (size_t)blockIdx.z * MTOT * G3;

    float* sbias = (float*)((char*)smh + 2 * BUF2);
    const uint32_t smu = s2u(smh);

    const int tid  = threadIdx.x;
    const int wid  = tid >> 5;
    const int lane = tid & 31;
    const int wm   = wid >> 2;
    const int wn   = wid & 3;
    const int gg   = lane >> 2;
    const int t    = lane & 3;
    const int rrow = lane & 7;
    const int grp  = lane >> 3;

    const size_t rowA0 = (size_t)blockIdx.y * 128;
    const int    ncol0 = blockIdx.x * 128;

    if (tid < 128) sbias[tid] = bias[ncol0 + tid];

    int lrow[2], lq[2];
#pragma unroll
    for (int p = 0; p < 2; p++) {
        int u = p * 256 + tid;
        lrow[p] = u >> 2;
        lq[p]   = u & 3;
    }

    float c[4][4][4];
#pragma unroll
    for (int i = 0; i < 4; i++)
#pragma unroll
        for (int j = 0; j < 4; j++)
#pragma unroll
            for (int q = 0; q < 4; q++) c[i][j][q] = 0.f;

    const int nkt = K / 32;

    auto load_tile = [&](int kt, int b) {
        uint32_t base = smu + (uint32_t)b * BUF2;
#pragma unroll
        for (int p = 0; p < 2; p++) {
            int row = lrow[p], q = lq[p];
            uint32_t doff = (uint32_t)(row * SA + q * 8) * 2;
            size_t ga = (rowA0 + row) * (size_t)K + (size_t)kt * 32 + q * 8;
            size_t gw = ((size_t)ncol0 + row) * (size_t)K + (size_t)kt * 32 + q * 8;
            cp16(base + doff,       Xf + ga);
            cp16(base + T2B + doff, W + gw);
        }
    };

    load_tile(0, 0);
    asm volatile("cp.async.commit_group;");

    const uint32_t a_lane = (uint32_t)((wm * 64 + rrow + (grp & 1) * 8) * SA + (grp >> 1) * 8);
    const uint32_t b_lane = (uint32_t)((wn * 32 + (grp >> 1) * 8 + rrow) * SA + (grp & 1) * 8);

    for (int kt = 0; kt < nkt; kt++) {
        if (kt + 1 < nkt) {
            load_tile(kt + 1, (kt + 1) & 1);
            asm volatile("cp.async.commit_group;");
            asm volatile("cp.async.wait_group 1;");
        } else {
            asm volatile("cp.async.wait_group 0;");
        }
        __syncthreads();

        const uint32_t buf = smu + (uint32_t)(kt & 1) * BUF2;

#pragma unroll
        for (int ks = 0; ks < 2; ks++) {
            const uint32_t kof2 = (uint32_t)(ks * 16) * 2;

            uint32_t fb[4][2];
#pragma unroll
            for (int jj = 0; jj < 2; jj++) {
                uint32_t ad = buf + T2B + (b_lane + (uint32_t)(jj * 16 * SA)) * 2 + kof2;
                ldsm4(fb[2 * jj][0], fb[2 * jj][1],
                      fb[2 * jj + 1][0], fb[2 * jj + 1][1], ad);
            }
            uint32_t fa[4][4];
#pragma unroll
            for (int i = 0; i < 4; i++) {
                uint32_t ad = buf + (a_lane + (uint32_t)(i * 16 * SA)) * 2 + kof2;
                ldsm4(fa[i][0], fa[i][1], fa[i][2], fa[i][3], ad);
            }
#pragma unroll
            for (int i = 0; i < 4; i++)
#pragma unroll
                for (int j = 0; j < 4; j++)
                    mma16816h(c[i][j], fa[i][0], fa[i][1], fa[i][2], fa[i][3],
                              fb[j][0], fb[j][1]);
        }
        __syncthreads();
    }

#pragma unroll
    for (int i = 0; i < 4; i++) {
        size_t r0 = rowA0 + wm * 64 + i * 16 + gg;
        size_t r1 = r0 + 8;
#pragma unroll
        for (int j = 0; j < 4; j++) {
            int cl = wn * 32 + j * 8 + 2 * t;
            float b0v = sbias[cl], b1v = sbias[cl + 1];
            *(float2*)(C + r0 * G3 + ncol0 + cl) =
                make_float2(c[i][j][0] + b0v, c[i][j][1] + b1v);
            *(float2*)(C + r1 * G3 + ncol0 + cl) =
                make_float2(c[i][j][2] + b0v, c[i][j][3] + b1v);
        }
    }
}

// =======================================================================
// Layer-1 GEMM: fp16 2-combo.  C = X*Wh + X*Wl + bias  (W exact hi/lo)
// Verified R15 structure (one A array, 4 stages).
// =======================================================================
#define BUF3 (3 * T2B)        // X, Yh, Yl  (30720 B)
#define HG2_SMEM (2 * BUF3 + 512)

__global__ __launch_bounds__(256, 2)
void hmma_gemm_2c(const __half* __restrict__ Xf, int K,
                  const __half* __restrict__ Wh0, const __half* __restrict__ Wl0,
                  const float* __restrict__ b0,
                  const __half* __restrict__ Wh1, const __half* __restrict__ Wl1,
                  const float* __restrict__ b1)
{
    extern __shared__ __half smh[];
    const __half* Wh = blockIdx.z ? Wh1 : Wh0;
    const __half* Wl = blockIdx.z ? Wl1 : Wl0;
    const float* bias = blockIdx.z ? b1 : b0;
    float* C = g_xp + (size_t)blockIdx.z * MTOT * G3;

    float* sbias = (float*)((char*)smh + 2 * BUF3);
    const uint32_t smu = s2u(smh);

    const int tid  = threadIdx.x;
    const int wid  = tid >> 5;
    const int lane = tid & 31;
    const int wm   = wid >> 2;
    const int wn   = wid & 3;
    const int gg   = lane >> 2;
    const int t    = lane & 3;
    const int rrow = lane & 7;
    const int grp  = lane >> 3;

    const size_t rowA0 = (size_t)blockIdx.y * 128;
    const int    ncol0 = blockIdx.x * 128;

    if (tid < 128) sbias[tid] = bias[ncol0 + tid];

    int lrow[2], lq[2];
#pragma unroll
    for (int p = 0; p < 2; p++) {
        int u = p * 256 + tid;
        lrow[p] = u >> 2;
        lq[p]   = u & 3;
    }

    float c[4][4][4];
#pragma unroll
    for (int i = 0; i < 4; i++)
#pragma unroll
        for (int j = 0; j < 4; j++)
#pragma unroll
            for (int q = 0; q < 4; q++) c[i][j][q] = 0.f;

    const int nkt = K / 32;

    auto load_tile = [&](int kt, int b) {
        uint32_t base = smu + (uint32_t)b * BUF3;
#pragma unroll
        for (int p = 0; p < 2; p++) {
            int row = lrow[p], q = lq[p];
            uint32_t doff = (uint32_t)(row * SA + q * 8) * 2;
            size_t ga = (rowA0 + row) * (size_t)K + (size_t)kt * 32 + q * 8;
            size_t gw = ((size_t)ncol0 + row) * (size_t)K + (size_t)kt * 32 + q * 8;
            cp16(base + doff,           Xf + ga);
            cp16(base + T2B + doff,     Wh + gw);
            cp16(base + 2 * T2B + doff, Wl + gw);
        }
    };

    load_tile(0, 0);
    asm volatile("cp.async.commit_group;");

    const uint32_t a_lane = (uint32_t)((wm * 64 + rrow + (grp & 1) * 8) * SA + (grp >> 1) * 8);
    const uint32_t b_lane = (uint32_t)((wn * 32 + (grp >> 1) * 8 + rrow) * SA + (grp & 1) * 8);

    for (int kt = 0; kt < nkt; kt++) {
        if (kt + 1 < nkt) {
            load_tile(kt + 1, (kt + 1) & 1);
            asm volatile("cp.async.commit_group;");
            asm volatile("cp.async.wait_group 1;");
        } else {
            asm volatile("cp.async.wait_group 0;");
        }
        __syncthreads();

        const uint32_t buf = smu + (uint32_t)(kt & 1) * BUF3;

#pragma unroll
        for (int s = 0; s < 4; s++) {
            const int combo = s >> 1, ks = s & 1;
            const uint32_t Wb = buf + (combo ? 2 * T2B : T2B);
            const uint32_t kof2 = (uint32_t)(ks * 16) * 2;

            uint32_t fb[4][2];
#pragma unroll
            for (int jj = 0; jj < 2; jj++) {
                uint32_t ad = Wb + (b_lane + (uint32_t)(jj * 16 * SA)) * 2 + kof2;
                ldsm4(fb[2 * jj][0], fb[2 * jj][1],
                      fb[2 * jj + 1][0], fb[2 * jj + 1][1], ad);
            }
            uint32_t fa[4][4];
#pragma unroll
            for (int i = 0; i < 4; i++) {
                uint32_t ad = buf + (a_lane + (uint32_t)(i * 16 * SA)) * 2 + kof2;
                ldsm4(fa[i][0], fa[i][1], fa[i][2], fa[i][3], ad);
            }
#pragma unroll
            for (int i = 0; i < 4; i++)
#pragma unroll
                for (int j = 0; j < 4; j++)
                    mma16816h(c[i][j], fa[i][0], fa[i][1], fa[i][2], fa[i][3],
                              fb[j][0], fb[j][1]);
        }
        __syncthreads();
    }

#pragma unroll
    for (int i = 0; i < 4; i++) {
        size_t r0 = rowA0 + wm * 64 + i * 16 + gg;
        size_t r1 = r0 + 8;
#pragma unroll
        for (int j = 0; j < 4; j++) {
            int cl = wn * 32 + j * 8 + 2 * t;
            float b0v = sbias[cl], b1v = sbias[cl + 1];
            *(float2*)(C + r0 * G3 + ncol0 + cl) =
                make_float2(c[i][j][0] + b0v, c[i][j][1] + b1v);
            *(float2*)(C + r1 * G3 + ncol0 + cl) =
                make_float2(c[i][j][2] + b0v, c[i][j][3] + b1v);
        }
    }
}

// =======================================================================
// GRU sequential scan (verified R14/R15 structure).
// x1 now stored as SINGLE fp16 (deferred one step).
// =======================================================================
__global__ __launch_bounds__(384, 1)
void gru_scan(const float* __restrict__ WhhF, const float* __restrict__ bhhF,
              const float* __restrict__ WhhB, const float* __restrict__ bhhB,
              int write_x1, int write_hN, int ndir)
{
    int bid = blockIdx.x;
    int dir, b;
    if (ndir == 2) { dir = bid >> 6; b = bid & 63; }
    else           { dir = 1;        b = bid; }

    const float* Whh = dir ? WhhB : WhhF;
    const float* bhh = dir ? bhhB : bhhF;
    const float* xp = g_xp + ((size_t)((ndir == 2) ? dir : 0) * B_ + b) * (size_t)T_ * G3;

    const int j = threadIdx.x;
    const bool is_gate = (j < H_);
    const bool is_z    = (j >= H_ && j < 2 * H_);

    __shared__ __align__(16) float sh_h[H_];
    __shared__ float sh_g[G3];
    __shared__ float sh_xn[H_];

    unsigned long long w[H_ / 2];
    {
        const unsigned long long* wr =
            (const unsigned long long*)(Whh + (size_t)j * H_);
#pragma unroll
        for (int k = 0; k < H_ / 2; k++) w[k] = wr[k];
    }
    const float bj = bhh[j];
    if (is_gate) sh_h[j] = 0.f;
    float h_reg = 0.f;
    __syncthreads();

    const int t0 = dir ? (T_ - 1) : 0;
    const int dt = dir ? -1 : 1;
    const ulonglong2* h4 = (const ulonglong2*)sh_h;

    float xv0 = xp[(size_t)t0 * G3 + j];
    float xv1 = (T_ > 1) ? xp[(size_t)(t0 + dt) * G3 + j] : 0.f;

    float pend_h = 0.f;
    int   pend_t = -1;
    __half* const x1_row = g_x1f + (size_t)b * T_ * (2 * H_) + (size_t)dir * H_ + j;

    for (int s = 0; s < T_; s++) {
        const int t = t0 + s * dt;
        float xv2 = 0.f;
        if (s + 2 < T_) xv2 = xp[(size_t)(t + 2 * dt) * G3 + j];

        if (write_x1 && is_gate && pend_t >= 0)
            x1_row[(size_t)pend_t * (2 * H_)] = __float2half(pend_h);

        unsigned long long a0 = 0ull, a1 = 0ull, a2 = 0ull, a3 = 0ull;
#pragma unroll
        for (int k = 0; k < H_ / 8; k++) {
            ulonglong2 hv0 = h4[2 * k];
            ulonglong2 hv1 = h4[2 * k + 1];
            a0 = ffma2(hv0.x, w[4 * k],     a0);
            a1 = ffma2(hv0.y, w[4 * k + 1], a1);
            a2 = ffma2(hv1.x, w[4 * k + 2], a2);
            a3 = ffma2(hv1.y, w[4 * k + 3], a3);
        }
        float2 p0 = u2f(a0), p1 = u2f(a1), p2 = u2f(a2), p3 = u2f(a3);
        float gsum = (p0.x + p0.y) + (p1.x + p1.y) +
                     (p2.x + p2.y) + (p3.x + p3.y) + bj;

        if (is_gate) {
            float r = sigmoid_fast(gsum + xv0);
            asm volatile("bar.sync 1, 384;" ::: "memory");
            float z  = sh_g[H_ + j];
            float n  = tanh_fast(sh_xn[j] + r * sh_g[2 * H_ + j]);
            float hn = (1.0f - z) * n + z * h_reg;
            h_reg = hn;
            sh_h[j] = hn;
            pend_h = hn;
            pend_t = t;
        } else {
            if (is_z) { sh_g[j] = sigmoid_fast(gsum + xv0); }
            else      { sh_g[j] = gsum; sh_xn[j - 2 * H_] = xv0; }
            asm volatile("bar.arrive 1, 384;" ::: "memory");
        }
        __syncthreads();
        xv0 = xv1;
        xv1 = xv2;
    }

    if (write_x1 && is_gate && pend_t >= 0)
        x1_row[(size_t)pend_t * (2 * H_)] = __float2half(pend_h);

    if (write_hN && is_gate) g_hN[b * H_ + j] = h_reg;
}

// =======================================================================
// Decoder (unchanged)
// =======================================================================
__device__ __forceinline__ float mishf(float x) {
    float sp = (x > 20.f) ? x : log1pf(expf(x));
    return x * tanhf(sp);
}
__device__ __forceinline__ float blockReduceSum(float v) {
#pragma unroll
    for (int o = 16; o > 0; o >>= 1) v += __shfl_xor_sync(0xffffffffu, v, o);
    __shared__ float s[4];
    int w = threadIdx.x >> 5;
    if ((threadIdx.x & 31) == 0) s[w] = v;
    __syncthreads();
    v = s[0] + s[1] + s[2] + s[3];
    __syncthreads();
    return v;
}

__global__ __launch_bounds__(128, 1)
void decoder(const float* __restrict__ g1, const float* __restrict__ be1,
             const float* __restrict__ W1, const float* __restrict__ b1,
             const float* __restrict__ g2, const float* __restrict__ be2,
             const float* __restrict__ W2, const float* __restrict__ b2,
             float* __restrict__ out)
{
    const int b = blockIdx.x, j = threadIdx.x;
    __shared__ float sv[H_];

    float v = mishf(g_hN[b * H_ + j]);
    float m = blockReduceSum(v) * (1.0f / H_);
    float d = v - m;
    float var = blockReduceSum(d * d) * (1.0f / H_);
    float y = d * rsqrtf(var + EPS_) * g1[j] + be1[j];
    sv[j] = y;
    __syncthreads();

    float t = b1[j];
#pragma unroll 4
    for (int k = 0; k < H_; k++) t = fmaf(sv[k], W1[j * H_ + k], t);
    float u = mishf(t);
    __syncthreads();

    m = blockReduceSum(u) * (1.0f / H_);
    d = u - m;
    var = blockReduceSum(d * d) * (1.0f / H_);
    float zz = d * rsqrtf(var + EPS_) * g2[j] + be2[j];

    float p = blockReduceSum(zz * W2[j]);
    if (j == 0) out[b] = p + b2[0];
}

// =======================================================================
// Host launcher
// =======================================================================
extern "C" void kernel_launch(void* const* d_in, const int* in_sizes, int n_in,
                              void* d_out, int out_size)
{
    (void)in_sizes; (void)n_in; (void)out_size;
    const float* x     = (const float*)d_in[0];
    const float* Wih0f = (const float*)d_in[1];
    const float* Whh0f = (const float*)d_in[2];
    const float* bih0f = (const float*)d_in[3];
    const float* bhh0f = (const float*)d_in[4];
    const float* Wih0b = (const float*)d_in[5];
    const float* Whh0b = (const float*)d_in[6];
    const float* bih0b = (const float*)d_in[7];
    const float* bhh0b = (const float*)d_in[8];
    // d_in[9..12] = layer-1 forward params: unused by the reference output
    const float* Wih1b = (const float*)d_in[13];
    const float* Whh1b = (const float*)d_in[14];
    const float* bih1b = (const float*)d_in[15];
    const float* bhh1b = (const float*)d_in[16];
    const float* g1  = (const float*)d_in[17];
    const float* be1 = (const float*)d_in[18];
    const float* W1  = (const float*)d_in[19];
    const float* b1  = (const float*)d_in[20];
    const float* g2  = (const float*)d_in[21];
    const float* be2 = (const float*)d_in[22];
    const float* W2  = (const float*)d_in[23];
    const float* b2  = (const float*)d_in[24];

    __half *xf, *w0f, *w0b, *x1f, *w1bh, *w1bl;
    cudaGetSymbolAddress((void**)&xf,   g_xf);
    cudaGetSymbolAddress((void**)&w0f,  g_w0f16);
    cudaGetSymbolAddress((void**)&w0b,  g_w0b16);
    cudaGetSymbolAddress((void**)&x1f,  g_x1f);
    cudaGetSymbolAddress((void**)&w1bh, g_w1bh16);
    cudaGetSymbolAddress((void**)&w1bl, g_w1bl16);

    static int smem_set = 0;
    if (!smem_set) {
        cudaFuncSetAttribute(hmma_gemm_1c,
                             cudaFuncAttributeMaxDynamicSharedMemorySize, HG1_SMEM);
        cudaFuncSetAttribute(hmma_gemm_2c,
                             cudaFuncAttributeMaxDynamicSharedMemorySize, HG2_SMEM);
        smem_set = 1;
    }

    // conversions
    conv_f16<<<4096, 256>>>(x, xf, (size_t)MTOT * IN_);
    conv_f16<<<64, 256>>>(Wih0f, w0f, (size_t)G3 * IN_);
    conv_f16<<<64, 256>>>(Wih0b, w0b, (size_t)G3 * IN_);
    split_f16<<<32, 256>>>(Wih1b, w1bh, w1bl, (size_t)G3 * 2 * H_);

    // layer-0 projections: fp16 1-combo
    {
        dim3 grid(3, MTOT / 128, 2);
        hmma_gemm_1c<<<grid, 256, HG1_SMEM>>>(xf, IN_, w0f, bih0f, w0b, bih0b);
    }
    gru_scan<<<128, 384>>>(Whh0f, bhh0f, Whh0b, bhh0b, 1, 0, 2);
    // layer-1 backward projection: fp16 2-combo
    {
        dim3 grid(3, MTOT / 128, 1);
        hmma_gemm_2c<<<grid, 256, HG2_SMEM>>>(x1f, 2 * H_,
                                              w1bh, w1bl, bih1b,
                                              w1bh, w1bl, bih1b);
    }
    gru_scan<<<64, 384>>>(Whh1b, bhh1b, Whh1b, bhh1b, 0, 1, 1);
    decoder<<<64, 128>>>(g1, be1, W1, b1, g2, be2, W2, b2, (float*)d_out);
}